// round 10
// baseline (speedup 1.0000x reference)
#include <cuda_runtime.h>
#include <cuda_fp16.h>
#include <math.h>
#include <stdint.h>

#define BSZ 1024
#define SLOTS 74   // 148-CTA persistent grid, 74 slots per N-half

// ---------------------------------------------------------------------------
// Global scratch (static __device__ arrays, allocation-free)
// ---------------------------------------------------------------------------
__device__ float g_ctb[BSZ * 256];              // b0 + temb @ W0[6:134]
__device__ __half g_h2[(size_t)BSZ * 256 * 256];
__device__ __half g_W[2 * 256 * 256];           // W^T fp16, [l][n][k]

// ---------------------------------------------------------------------------
// PTX helpers (sm_75/80-era: valid on the harness's sm_103 target)
// ---------------------------------------------------------------------------
__device__ __forceinline__ uint32_t s2u(const void* p) {
    uint32_t a;
    asm("{ .reg .u64 t; cvta.to.shared.u64 t, %1; cvt.u32.u64 %0, t; }"
        : "=r"(a) : "l"(p));
    return a;
}
#define CP_ASYNC16(dst, src) \
    asm volatile("cp.async.cg.shared.global [%0], [%1], 16;" :: "r"(dst), "l"(src))
#define CP_COMMIT() asm volatile("cp.async.commit_group;" ::: "memory")
#define CP_WAIT(n)  asm volatile("cp.async.wait_group %0;" :: "n"(n) : "memory")

__device__ __forceinline__ void ldsm4(uint32_t& r0, uint32_t& r1, uint32_t& r2,
                                      uint32_t& r3, uint32_t a) {
    asm volatile("ldmatrix.sync.aligned.m8n8.x4.shared.b16 {%0,%1,%2,%3}, [%4];"
                 : "=r"(r0), "=r"(r1), "=r"(r2), "=r"(r3) : "r"(a));
}
__device__ __forceinline__ void mma16816(float* d, const uint32_t* a,
                                         uint32_t b0, uint32_t b1) {
    asm volatile(
        "mma.sync.aligned.m16n8k16.row.col.f32.f16.f16.f32 "
        "{%0,%1,%2,%3}, {%4,%5,%6,%7}, {%8,%9}, {%0,%1,%2,%3};"
        : "+f"(d[0]), "+f"(d[1]), "+f"(d[2]), "+f"(d[3])
        : "r"(a[0]), "r"(a[1]), "r"(a[2]), "r"(a[3]), "r"(b0), "r"(b1));
}
// silu via single-MUFU tanh.approx: x*sigmoid(x) = 0.5x*tanh(0.5x) + 0.5x
__device__ __forceinline__ float fsilu(float x) {
    float t, h = 0.5f * x;
    asm("tanh.approx.f32 %0, %1;" : "=f"(t) : "f"(h));
    return fmaf(h, t, h);
}

// ---------------------------------------------------------------------------
// Kernel: prep (merged). Blocks 0..511: weights->fp16 transposed.
// Blocks 512..1535: per-batch time embedding -> g_ctb.
// ---------------------------------------------------------------------------
__global__ void __launch_bounds__(256) k_prep(
    const float* __restrict__ W1, const float* __restrict__ W2,
    const float* __restrict__ t, const float* __restrict__ tw,
    const float* __restrict__ tb, const float* __restrict__ W0,
    const float* __restrict__ b0) {
    int bb = blockIdx.x, tid = threadIdx.x;
    if (bb < 512) {
        int l = bb >> 8, k = bb & 255;
        const float* W = l ? W2 : W1;
        g_W[l * 65536 + tid * 256 + k] = __float2half(W[k * 256 + tid]);
        return;
    }
    int b = bb - 512;
    __shared__ float emb[128];
    __shared__ float te[128];
    if (tid < 64) {
        float fr = expf(-9.210340371976184f * (float)tid / 63.0f);
        float a = t[b] * fr;
        emb[tid]      = sinf(a);
        emb[tid + 64] = cosf(a);
    }
    __syncthreads();
    if (tid < 128) {
        float acc = tb[tid];
#pragma unroll 8
        for (int i = 0; i < 128; i++) acc += emb[i] * tw[i * 128 + tid];
        te[tid] = acc / (1.0f + expf(-acc));
    }
    __syncthreads();
    {
        float a2 = b0[tid];
#pragma unroll 8
        for (int k = 0; k < 128; k++) a2 += te[k] * W0[(6 + k) * 256 + tid];
        g_ctb[b * 256 + tid] = a2;
    }
}

// ---------------------------------------------------------------------------
// FUSED layer0+layer1 persistent kernel. grid = 148, block = 512.
// CTA pinned to nh; loops over b = slot + i*74. B (W1^T half) resident.
// Per K-chunk of 64, the CTA COMPUTES the layer-0 output tile
//   h~0[v][k] = roll3_v( silu( xa[v]w0k + ya[v]w1k + scf[v].w2..5k + ctb[k] ) )/3
// directly into a swizzled smem ping-pong A buffer (rank-6 algebra, no table),
// then runs the MMA on it. x/ctb prefetched one tile ahead via cp.async.
// Epilogue: bias+silu in regs -> swizzled stage -> roll -> g_h2.
// ---------------------------------------------------------------------------
__global__ void __launch_bounds__(512, 1) k_mma_l1(
    const float* __restrict__ x, const float* __restrict__ W0,
    const __half* __restrict__ B, const float* __restrict__ bias,
    __half* __restrict__ O) {
    extern __shared__ __align__(1024) char smc[];
    const uint32_t smb = s2u(smc);
    const int tid = threadIdx.x, wid = tid >> 5, lane = tid & 31;
    const int nh = blockIdx.x & 1, slot = blockIdx.x >> 1;
    const int wm = wid >> 2, wn = wid & 3;

    // smem map (bytes):
    //   A ping-pong 2 x 32768 @ 0 ; B 65536 @ 65536 ; stage 65536 @ 131072
    //   xs2 2x2048 @ 196608 ; ctb2 2x1024 @ 200704 ; xa 1024 @ 202752
    //   ya 1024 @ 203776 ; scf 4096 @ 204800 ; w8 8192 @ 208896  (end 217088)
    const uint32_t OFF_B = 65536u, OFF_S = 131072u, OFF_X = 196608u,
                   OFF_CT = 200704u;
    float*  xaA  = (float*)(smc + 202752);
    float*  yaA  = (float*)(smc + 203776);
    float4* scf4 = (float4*)(smc + 204800);
    float*  w8A  = (float*)(smc + 208896);

    const __half* Bgl = B;   // already offset by caller per nh? no: offset here
    Bgl += nh * 32768;

    const int nt = (1024 - slot + 73) / 74;

#define ISSUE_XC(BIDX, BUF)                                                  \
    do {                                                                     \
        if (tid < 128)                                                       \
            CP_ASYNC16(smb + OFF_X + (uint32_t)(BUF) * 2048u + tid * 16,     \
                       x + (size_t)(BIDX) * 512 + tid * 4);                  \
        else if (tid < 192)                                                  \
            CP_ASYNC16(smb + OFF_CT + (uint32_t)(BUF) * 1024u + (tid - 128) * 16, \
                       g_ctb + (size_t)(BIDX) * 256 + (tid - 128) * 4);      \
    } while (0)

    // ---- one-time prologue ----
#pragma unroll
    for (int j = 0; j < 8; j++) {
        int idx = tid + j * 512;
        int cS = idx >> 10, row = (idx >> 3) & 127, acb = idx & 7;
        uint32_t swc = (uint32_t)((acb * 16) ^ ((row & 7) << 4));
        CP_ASYNC16(smb + OFF_B + cS * 16384 + row * 128 + swc,
                   Bgl + row * 256 + cS * 64 + acb * 8);
    }
    CP_COMMIT();
    if (tid < 256) {
        int k = tid;
#pragma unroll
        for (int j = 0; j < 6; j++) w8A[k * 8 + j] = W0[j * 256 + k];
    } else {
        int v = tid - 256;
        const float dth = 6.283185307179586f / 256.0f;
        float f1 = (1.0f + 2.0f * cosf(dth)) / 3.0f;
        float f2 = (1.0f + 2.0f * cosf(2.0f * dth)) / 3.0f;
        float th = dth * (float)v;
        float s1, c1, s2, c2;
        sincosf(th, &s1, &c1);
        sincosf(2.0f * th, &s2, &c2);
        scf4[v] = make_float4(f1 * s1, f1 * c1, f2 * s2, f2 * c2);
    }
    ISSUE_XC(slot, 0);
    CP_COMMIT();
    CP_WAIT(0);
    __syncthreads();

    // ldsm addressing
    const int li = lane >> 3, lr = lane & 7;
    uint32_t colk[4];
#pragma unroll
    for (int kt = 0; kt < 4; kt++)
        colk[kt] = (uint32_t)((kt * 32 + (li >> 1) * 16) ^ (lr << 4));
    const uint32_t aRow = smb + (uint32_t)(wm * 64 + (li & 1) * 8 + lr) * 128;
    const uint32_t bRow = smb + OFF_B + (uint32_t)(wn * 32 + (li & 1) * 8 + lr) * 128;

    // bias regs
    const int r = lane >> 2, l2 = (lane & 3) * 2;
    float bj[4][2];
#pragma unroll
    for (int nt2 = 0; nt2 < 4; nt2++) {
        int n = nh * 128 + wn * 32 + nt2 * 8 + l2;
        bj[nt2][0] = bias[n];
        bj[nt2][1] = bias[n + 1];
    }

    // compute-phase thread mapping: kp = lane (k-pair), warp = v-group of 16
    const int kp = lane, vg16 = wid * 16;

    for (int i = 0; i < nt; i++) {
        const int b = slot + i * SLOTS;
        const int buf = i & 1;

        if (i > 0) CP_WAIT(0);
        __syncthreads();   // xs/ctb for tile i visible
        if (tid < 256) {
            const float2* xf = (const float2*)(smc + OFF_X + buf * 2048);
            int v = tid, vm = (v + 255) & 255, vp = (v + 1) & 255;
            float2 xm = xf[vm], xc = xf[v], xp = xf[vp];
            xaA[v] = (xm.x + xc.x + xp.x) * (1.0f / 3.0f);
            yaA[v] = (xm.y + xc.y + xp.y) * (1.0f / 3.0f);
        }
        __syncthreads();
        if (i + 1 < nt) ISSUE_XC(b + SLOTS, 1 - buf);
        CP_COMMIT();

        const float* ctbA = (const float*)(smc + OFF_CT + buf * 1024);

        float acc[4][4][4];
#pragma unroll
        for (int mt = 0; mt < 4; mt++)
#pragma unroll
            for (int nt2 = 0; nt2 < 4; nt2++)
#pragma unroll
                for (int q = 0; q < 4; q++) acc[mt][nt2][q] = 0.0f;

        for (int c = 0; c < 4; c++) {
            // ---- compute A chunk c (layer-0 algebra) into ping-pong buf ----
            {
                char* abuf = smc + (c & 1) * 32768;
                int k0 = c * 64 + 2 * kp;
                float wk[12];
                const float* wp = w8A + k0 * 8;
#pragma unroll
                for (int q = 0; q < 6; q++) { wk[q] = wp[q]; wk[6 + q] = wp[8 + q]; }
                float cb0 = ctbA[k0], cb1 = ctbA[k0 + 1];

#define HEV(VV, H0, H1)                                                      \
    do {                                                                     \
        int _v = (VV) & 255;                                                 \
        float _xa = xaA[_v], _ya = yaA[_v];                                  \
        float4 _sc = scf4[_v];                                               \
        float _a0 = fmaf(_xa, wk[0], fmaf(_ya, wk[1],                        \
                    fmaf(_sc.x, wk[2], fmaf(_sc.y, wk[3],                    \
                    fmaf(_sc.z, wk[4], fmaf(_sc.w, wk[5], cb0))))));         \
        float _a1 = fmaf(_xa, wk[6], fmaf(_ya, wk[7],                        \
                    fmaf(_sc.x, wk[8], fmaf(_sc.y, wk[9],                    \
                    fmaf(_sc.z, wk[10], fmaf(_sc.w, wk[11], cb1))))));       \
        H0 = fsilu(_a0); H1 = fsilu(_a1);                                    \
    } while (0)

                float hm0, hm1, hc0, hc1, hp0, hp1;
                HEV(vg16 + 255, hm0, hm1);
                HEV(vg16, hc0, hc1);
#pragma unroll
                for (int v = vg16; v < vg16 + 16; v++) {
                    HEV(v + 1, hp0, hp1);
                    float t0 = (hm0 + hc0 + hp0) * (1.0f / 3.0f);
                    float t1 = (hm1 + hc1 + hp1) * (1.0f / 3.0f);
                    *(__half2*)(abuf + v * 128 + ((4 * kp) ^ ((v & 7) << 4))) =
                        __floats2half2_rn(t0, t1);
                    hm0 = hc0; hm1 = hc1; hc0 = hp0; hc1 = hp1;
                }
#undef HEV
            }
            __syncthreads();   // A chunk ready; prior MMA (c-2 buf) long done

            // ---- MMA chunk c ----
            const uint32_t aB = aRow + (uint32_t)(c & 1) * 32768u;
            const uint32_t bB = bRow + (uint32_t)c * 16384u;
#pragma unroll
            for (int kt = 0; kt < 4; kt++) {
                uint32_t ah[4][4];
#pragma unroll
                for (int mt = 0; mt < 4; mt++)
                    ldsm4(ah[mt][0], ah[mt][1], ah[mt][2], ah[mt][3],
                          aB + mt * 2048 + colk[kt]);
#pragma unroll
                for (int p = 0; p < 2; p++) {
                    uint32_t bh[4];
                    ldsm4(bh[0], bh[1], bh[2], bh[3], bB + p * 2048 + colk[kt]);
#pragma unroll
                    for (int mt = 0; mt < 4; mt++)
#pragma unroll
                        for (int s = 0; s < 2; s++)
                            mma16816(acc[mt][p * 2 + s], ah[mt], bh[s], bh[2 + s]);
                }
            }
        }

        // ---- epilogue: silu in regs -> swizzled stage -> roll -> gmem ----
#pragma unroll
        for (int mt = 0; mt < 4; mt++)
#pragma unroll
            for (int nt2 = 0; nt2 < 4; nt2++) {
                int v = wm * 64 + mt * 16 + r;
                uint32_t scol = (uint32_t)(((wn * 32 + nt2 * 8 + l2) * 2) ^ (r << 4));
                *(__half2*)(smc + OFF_S + v * 256 + scol) = __floats2half2_rn(
                    fsilu(acc[mt][nt2][0] + bj[nt2][0]),
                    fsilu(acc[mt][nt2][1] + bj[nt2][1]));
                *(__half2*)(smc + OFF_S + (v + 8) * 256 + scol) = __floats2half2_rn(
                    fsilu(acc[mt][nt2][2] + bj[nt2][0]),
                    fsilu(acc[mt][nt2][3] + bj[nt2][1]));
            }
        __syncthreads();
        {
            int np = tid & 63, vgE = tid >> 6;
            __half* Og = O + (size_t)b * 65536 + nh * 128 + 2 * np;
            const __half2 third = __floats2half2_rn(1.0f / 3.0f, 1.0f / 3.0f);
#pragma unroll 4
            for (int v = vgE * 32; v < vgE * 32 + 32; v++) {
                int vm = (v + 255) & 255, vp = (v + 1) & 255;
                __half2 a2 = *(const __half2*)(smc + OFF_S + vm * 256 +
                                               ((4 * np) ^ ((vm & 7) << 4)));
                __half2 b2 = *(const __half2*)(smc + OFF_S + v * 256 +
                                               ((4 * np) ^ ((v & 7) << 4)));
                __half2 c2 = *(const __half2*)(smc + OFF_S + vp * 256 +
                                               ((4 * np) ^ ((vp & 7) << 4)));
                *(__half2*)(Og + (size_t)v * 256) =
                    __hmul2(__hadd2(__hadd2(a2, b2), c2), third);
            }
        }
        __syncthreads();   // stage reads done before next tile's writes
    }
    CP_WAIT(0);
}

// ---------------------------------------------------------------------------
// Persistent fp16 mma.sync GCN layer (final). grid = 148, block = 512.
// Unchanged from R9: B resident, A streamed via 3-buffer cp.async ring.
// ---------------------------------------------------------------------------
__global__ void __launch_bounds__(512, 1) k_mma(
    const __half* __restrict__ A, const __half* __restrict__ B,
    const float* __restrict__ bias,
    __half* __restrict__ O, float* __restrict__ out, int is_final) {
    extern __shared__ __align__(1024) char smc[];
    const uint32_t smb = s2u(smc);
    const int tid = threadIdx.x, wid = tid >> 5, lane = tid & 31;
    const int nh = blockIdx.x & 1, slot = blockIdx.x >> 1;
    const int wm = wid >> 2, wn = wid & 3;

    const uint32_t OFF_B = 98304u, OFF_S = 163840u;

    const __half* Bgl = B + nh * 32768;

    const int nt = (1024 - slot + 73) / 74;
    const int NC = 4 * nt;

    const int ar = tid >> 3, ac = tid & 7;
    const uint32_t swcA = (uint32_t)((ac * 16) ^ ((ar & 7) << 4));

#define ISSUE_A(BIDX, CH, BUF)                                               \
    do {                                                                     \
        const __half* _Ag = A + (size_t)(BIDX) * 65536;                      \
        uint32_t _dst = smb + (uint32_t)(BUF) * 32768u;                      \
        _Pragma("unroll") for (int _j = 0; _j < 4; _j++) {                   \
            int _row = ar + _j * 64;                                         \
            CP_ASYNC16(_dst + _row * 128 + swcA,                             \
                       _Ag + _row * 256 + (CH) * 64 + ac * 8);               \
        }                                                                    \
    } while (0)

#pragma unroll
    for (int j = 0; j < 8; j++) {
        int idx = tid + j * 512;
        int cS = idx >> 10, row = (idx >> 3) & 127, acb = idx & 7;
        uint32_t swc = (uint32_t)((acb * 16) ^ ((row & 7) << 4));
        CP_ASYNC16(smb + OFF_B + cS * 16384 + row * 128 + swc,
                   Bgl + row * 256 + cS * 64 + acb * 8);
    }
    ISSUE_A(slot, 0, 0);
    CP_COMMIT();
    ISSUE_A(slot, 1, 1);
    CP_COMMIT();

    const int li = lane >> 3, lr = lane & 7;
    uint32_t colk[4];
#pragma unroll
    for (int kt = 0; kt < 4; kt++)
        colk[kt] = (uint32_t)((kt * 32 + (li >> 1) * 16) ^ (lr << 4));
    const uint32_t aRow = smb + (uint32_t)(wm * 64 + (li & 1) * 8 + lr) * 128;
    const uint32_t bRow = smb + OFF_B + (uint32_t)(wn * 32 + (li & 1) * 8 + lr) * 128;

    const int r = lane >> 2, l2 = (lane & 3) * 2;
    float bj[4][2];
#pragma unroll
    for (int nt2 = 0; nt2 < 4; nt2++) {
        int n = nh * 128 + wn * 32 + nt2 * 8 + l2;
        bj[nt2][0] = bias[n];
        bj[nt2][1] = bias[n + 1];
    }

    int g = 0;
    for (int i = 0; i < nt; i++) {
        const int b = slot + i * SLOTS;

        float acc[4][4][4];
#pragma unroll
        for (int mt = 0; mt < 4; mt++)
#pragma unroll
            for (int nt2 = 0; nt2 < 4; nt2++)
#pragma unroll
                for (int q = 0; q < 4; q++) acc[mt][nt2][q] = 0.0f;

        for (int c = 0; c < 4; c++) {
            CP_WAIT(1);
            __syncthreads();
            int gn = g + 2;
            if (gn < NC) ISSUE_A(slot + (gn >> 2) * SLOTS, gn & 3, gn % 3);
            CP_COMMIT();

            const uint32_t aB = aRow + (uint32_t)(g % 3) * 32768u;
            const uint32_t bB = bRow + (uint32_t)c * 16384u;
#pragma unroll
            for (int kt = 0; kt < 4; kt++) {
                uint32_t ah[4][4];
#pragma unroll
                for (int mt = 0; mt < 4; mt++)
                    ldsm4(ah[mt][0], ah[mt][1], ah[mt][2], ah[mt][3],
                          aB + mt * 2048 + colk[kt]);
#pragma unroll
                for (int p = 0; p < 2; p++) {
                    uint32_t bh[4];
                    ldsm4(bh[0], bh[1], bh[2], bh[3], bB + p * 2048 + colk[kt]);
#pragma unroll
                    for (int mt = 0; mt < 4; mt++)
#pragma unroll
                        for (int s = 0; s < 2; s++)
                            mma16816(acc[mt][p * 2 + s], ah[mt], bh[s], bh[2 + s]);
                }
            }
            g++;
        }

        if (!is_final) {
#pragma unroll
            for (int mt = 0; mt < 4; mt++)
#pragma unroll
                for (int nt2 = 0; nt2 < 4; nt2++) {
                    int v = wm * 64 + mt * 16 + r;
                    uint32_t scol = (uint32_t)(((wn * 32 + nt2 * 8 + l2) * 2) ^ (r << 4));
                    *(__half2*)(smc + OFF_S + v * 256 + scol) = __floats2half2_rn(
                        fsilu(acc[mt][nt2][0] + bj[nt2][0]),
                        fsilu(acc[mt][nt2][1] + bj[nt2][1]));
                    *(__half2*)(smc + OFF_S + (v + 8) * 256 + scol) = __floats2half2_rn(
                        fsilu(acc[mt][nt2][2] + bj[nt2][0]),
                        fsilu(acc[mt][nt2][3] + bj[nt2][1]));
                }
            __syncthreads();
            int np = tid & 63, vg = tid >> 6;
            __half* Og = O + (size_t)b * 65536 + nh * 128 + 2 * np;
            const __half2 third = __floats2half2_rn(1.0f / 3.0f, 1.0f / 3.0f);
#pragma unroll 4
            for (int v = vg * 32; v < vg * 32 + 32; v++) {
                int vm = (v + 255) & 255, vp = (v + 1) & 255;
                __half2 a2 = *(const __half2*)(smc + OFF_S + vm * 256 +
                                               ((4 * np) ^ ((vm & 7) << 4)));
                __half2 b2 = *(const __half2*)(smc + OFF_S + v * 256 +
                                               ((4 * np) ^ ((v & 7) << 4)));
                __half2 c2 = *(const __half2*)(smc + OFF_S + vp * 256 +
                                               ((4 * np) ^ ((vp & 7) << 4)));
                *(__half2*)(Og + (size_t)v * 256) =
                    __hmul2(__hadd2(__hadd2(a2, b2), c2), third);
            }
            __syncthreads();
        } else {
            float cs[4][2];
#pragma unroll
            for (int nt2 = 0; nt2 < 4; nt2++) { cs[nt2][0] = 0.0f; cs[nt2][1] = 0.0f; }
#pragma unroll
            for (int mt = 0; mt < 4; mt++)
#pragma unroll
                for (int nt2 = 0; nt2 < 4; nt2++) {
                    cs[nt2][0] += fsilu(acc[mt][nt2][0] + bj[nt2][0]) +
                                  fsilu(acc[mt][nt2][2] + bj[nt2][0]);
                    cs[nt2][1] += fsilu(acc[mt][nt2][1] + bj[nt2][1]) +
                                  fsilu(acc[mt][nt2][3] + bj[nt2][1]);
                }
#pragma unroll
            for (int off = 4; off <= 16; off <<= 1)
#pragma unroll
                for (int nt2 = 0; nt2 < 4; nt2++) {
                    cs[nt2][0] += __shfl_xor_sync(0xFFFFFFFFu, cs[nt2][0], off);
                    cs[nt2][1] += __shfl_xor_sync(0xFFFFFFFFu, cs[nt2][1], off);
                }
            float* red = (float*)(smc + OFF_S);
            if (r == 0) {
#pragma unroll
                for (int nt2 = 0; nt2 < 4; nt2++) {
                    int n = wn * 32 + nt2 * 8 + l2;
                    red[wm * 128 + n]     = cs[nt2][0];
                    red[wm * 128 + n + 1] = cs[nt2][1];
                }
            }
            __syncthreads();
            if (tid < 128)
                out[b * 256 + nh * 128 + tid] =
                    (red[tid] + red[128 + tid] + red[256 + tid] + red[384 + tid]) *
                    (1.0f / 256.0f);
            __syncthreads();
        }
    }
    CP_WAIT(0);
}

// ---------------------------------------------------------------------------
extern "C" void kernel_launch(void* const* d_in, const int* in_sizes, int n_in,
                              void* d_out, int out_size) {
    const float* x  = (const float*)d_in[0];
    const float* t  = (const float*)d_in[1];
    const float* tw = (const float*)d_in[2];
    const float* tb = (const float*)d_in[3];
    const float* W0 = (const float*)d_in[4];
    const float* b0 = (const float*)d_in[5];
    const float* W1 = (const float*)d_in[6];
    const float* b1 = (const float*)d_in[7];
    const float* W2 = (const float*)d_in[8];
    const float* b2 = (const float*)d_in[9];
    float* out = (float*)d_out;

    cudaFuncSetAttribute(k_mma_l1, cudaFuncAttributeMaxDynamicSharedMemorySize, 217088);
    cudaFuncSetAttribute(k_mma,    cudaFuncAttributeMaxDynamicSharedMemorySize, 229376);

    __half *h2, *w;
    cudaGetSymbolAddress((void**)&h2, g_h2);
    cudaGetSymbolAddress((void**)&w,  g_W);

    k_prep<<<1536, 256>>>(W1, W2, t, tw, tb, W0, b0);
    k_mma_l1<<<148, 512, 217088>>>(x, W0, w, b1, h2);
    k_mma<<<148, 512, 229376>>>(h2, w + 65536, b2, nullptr, out, 1);
}

// round 11
// speedup vs baseline: 1.1804x; 1.1804x over previous
#include <cuda_runtime.h>
#include <cuda_fp16.h>
#include <math.h>
#include <stdint.h>

#define BSZ 1024
#define SLOTS 74   // 148-CTA persistent grid, 74 slots per N-half

// ---------------------------------------------------------------------------
// Global scratch (static __device__ arrays, allocation-free)
// ---------------------------------------------------------------------------
__device__ float g_ctb[BSZ * 256];              // b0 + temb @ W0[6:134]
__device__ __half g_peWsh[256 * 256];           // roll-averaged pe @ W0[2:6], fp16
__device__ __half g_h1[(size_t)BSZ * 256 * 256];
__device__ __half g_h2[(size_t)BSZ * 256 * 256];
__device__ __half g_W[2 * 256 * 256];           // W^T fp16, [l][n][k]

// ---------------------------------------------------------------------------
// PTX helpers (sm_75/80-era: valid on the harness's sm_103 target)
// ---------------------------------------------------------------------------
__device__ __forceinline__ uint32_t s2u(const void* p) {
    uint32_t a;
    asm("{ .reg .u64 t; cvta.to.shared.u64 t, %1; cvt.u32.u64 %0, t; }"
        : "=r"(a) : "l"(p));
    return a;
}
#define CP_ASYNC16(dst, src) \
    asm volatile("cp.async.cg.shared.global [%0], [%1], 16;" :: "r"(dst), "l"(src))
#define CP_COMMIT() asm volatile("cp.async.commit_group;" ::: "memory")
#define CP_WAIT(n)  asm volatile("cp.async.wait_group %0;" :: "n"(n) : "memory")

__device__ __forceinline__ void ldsm4(uint32_t& r0, uint32_t& r1, uint32_t& r2,
                                      uint32_t& r3, uint32_t a) {
    asm volatile("ldmatrix.sync.aligned.m8n8.x4.shared.b16 {%0,%1,%2,%3}, [%4];"
                 : "=r"(r0), "=r"(r1), "=r"(r2), "=r"(r3) : "r"(a));
}
__device__ __forceinline__ void mma16816(float* d, const uint32_t* a,
                                         uint32_t b0, uint32_t b1) {
    asm volatile(
        "mma.sync.aligned.m16n8k16.row.col.f32.f16.f16.f32 "
        "{%0,%1,%2,%3}, {%4,%5,%6,%7}, {%8,%9}, {%0,%1,%2,%3};"
        : "+f"(d[0]), "+f"(d[1]), "+f"(d[2]), "+f"(d[3])
        : "r"(a[0]), "r"(a[1]), "r"(a[2]), "r"(a[3]), "r"(b0), "r"(b1));
}
// silu via single-MUFU tanh.approx: x*sigmoid(x) = 0.5x*tanh(0.5x) + 0.5x
__device__ __forceinline__ float fsilu(float x) {
    float t, h = 0.5f * x;
    asm("tanh.approx.f32 %0, %1;" : "=f"(t) : "f"(h));
    return fmaf(h, t, h);
}

// ---------------------------------------------------------------------------
// Kernel: weights -> fp16, transposed to [n][k]
// ---------------------------------------------------------------------------
__global__ void k_wconv(const float* __restrict__ W1, const float* __restrict__ W2) {
    int bb = blockIdx.x;           // 0..511
    int l = bb >> 8, k = bb & 255;
    int n = threadIdx.x;           // 0..255
    const float* W = l ? W2 : W1;
    g_W[l * 65536 + n * 256 + k] = __float2half(W[k * 256 + n]);
}

// ---------------------------------------------------------------------------
// Kernel: time embedding -> ctb = b0 + silu(sin-emb @ time_w + time_b) @ W0[6:]
// ---------------------------------------------------------------------------
__global__ void k_temb(const float* __restrict__ t, const float* __restrict__ tw,
                       const float* __restrict__ tb, const float* __restrict__ W0,
                       const float* __restrict__ b0) {
    __shared__ float emb[128];
    __shared__ float te[128];
    int b = blockIdx.x, tid = threadIdx.x;
    if (tid < 64) {
        float fr = expf(-9.210340371976184f * (float)tid / 63.0f);
        float a = t[b] * fr;
        emb[tid]      = sinf(a);
        emb[tid + 64] = cosf(a);
    }
    __syncthreads();
    float acc = tb[tid];
#pragma unroll 8
    for (int i = 0; i < 128; i++) acc += emb[i] * tw[i * 128 + tid];
    te[tid] = acc / (1.0f + expf(-acc));
    __syncthreads();
    for (int j = tid; j < 256; j += 128) {
        float a2 = b0[j];
#pragma unroll 8
        for (int k = 0; k < 128; k++) a2 += te[k] * W0[(6 + k) * 256 + j];
        g_ctb[b * 256 + j] = a2;
    }
}

// ---------------------------------------------------------------------------
// Kernel: peWs[v][j] = roll-avg(pe) @ W0[2:6] (roll factors folded in), fp16
// ---------------------------------------------------------------------------
__global__ void k_pew(const float* __restrict__ W0) {
    int v = blockIdx.x, j = threadIdx.x;
    const float dth = 6.283185307179586f / 256.0f;
    float f1 = (1.0f + 2.0f * cosf(dth)) / 3.0f;
    float f2 = (1.0f + 2.0f * cosf(2.0f * dth)) / 3.0f;
    float th = dth * (float)v;
    float s1 = sinf(th), c1 = cosf(th);
    float s2 = sinf(2.0f * th), c2 = cosf(2.0f * th);
    g_peWsh[v * 256 + j] =
        __float2half(f1 * (s1 * W0[2 * 256 + j] + c1 * W0[3 * 256 + j]) +
                     f2 * (s2 * W0[4 * 256 + j] + c2 * W0[5 * 256 + j]));
}

// ---------------------------------------------------------------------------
// Kernel: layer 0 collapsed, fp32 math + f32 tanh, peW rows prefetched to
// smem via cp.async. v-EIGHTH split: smaller pws halo (34 rows, 17.4 KB)
// -> higher occupancy than the v-quarter version.
// grid = 8192 (b, v-eighth), block = 256 (128 col-pairs x 2 v-groups of 16).
// ---------------------------------------------------------------------------
__global__ void __launch_bounds__(256) k_layer0(const float* __restrict__ x,
                                                const float* __restrict__ W0) {
    __shared__ float xs[512];
    __shared__ float xa[256], ya[256];
    __shared__ __half pws[34 * 256];   // rows v0-1 .. v0+32 of peWsh (17408 B)
    int b = blockIdx.x >> 3, ve = blockIdx.x & 7;
    int tid = threadIdx.x;
    int v0e = ve * 32;

    // prefetch peW rows (wrap-around source rows -> linear smem rows)
    {
        uint32_t pb = s2u(pws);
        const char* src = (const char*)g_peWsh;
        int base = (v0e + 255) & 255;
        for (int i = tid; i < 34 * 32; i += 256) {
            int row = i >> 5, seg = i & 31;
            int vsrc = (base + row) & 255;
            CP_ASYNC16(pb + row * 512 + seg * 16, src + vsrc * 512 + seg * 16);
        }
        CP_COMMIT();
    }

    for (int i = tid; i < 512; i += 256) xs[i] = x[b * 512 + i];
    __syncthreads();
    {
        int v = tid, vm = (v + 255) & 255, vp = (v + 1) & 255;
        xa[v] = (xs[2 * vm] + xs[2 * v] + xs[2 * vp]) * (1.0f / 3.0f);
        ya[v] = (xs[2 * vm + 1] + xs[2 * v + 1] + xs[2 * vp + 1]) * (1.0f / 3.0f);
    }
    CP_WAIT(0);
    __syncthreads();

    int cp = tid & 127, vg = tid >> 7, c0 = 2 * cp;
    float w00 = W0[c0], w01 = W0[c0 + 1];
    float w10 = W0[256 + c0], w11 = W0[256 + c0 + 1];
    float cb0 = g_ctb[b * 256 + c0], cb1 = g_ctb[b * 256 + c0 + 1];
    int j0 = vg * 16 + 1;   // local row of first output v

#define HEVAL(JJ, H0, H1)                                                  \
    do {                                                                   \
        int _j = (JJ);                                                     \
        float2 pw = __half22float2(*(const __half2*)(pws + _j * 256 + c0));\
        int _v = (v0e + _j - 1) & 255;                                     \
        float _xv = xa[_v], _yv = ya[_v];                                  \
        float a0 = fmaf(_xv, w00, fmaf(_yv, w10, pw.x + cb0));             \
        float a1 = fmaf(_xv, w01, fmaf(_yv, w11, pw.y + cb1));             \
        H0 = fsilu(a0); H1 = fsilu(a1);                                    \
    } while (0)

    float hm0, hm1, hc0, hc1;
    HEVAL(j0 - 1, hm0, hm1);
    HEVAL(j0, hc0, hc1);
    __half* Og = g_h1 + (size_t)b * 65536 + (size_t)(v0e + vg * 16) * 256 + c0;
#pragma unroll 8
    for (int j = j0; j < j0 + 16; j++) {
        float hp0, hp1;
        HEVAL(j + 1, hp0, hp1);
        float t0 = (hm0 + hc0 + hp0) * (1.0f / 3.0f);
        float t1 = (hm1 + hc1 + hp1) * (1.0f / 3.0f);
        *(__half2*)Og = __floats2half2_rn(t0, t1);
        Og += 256;
        hm0 = hc0; hm1 = hc1; hc0 = hp0; hc1 = hp1;
    }
#undef HEVAL
}

// ---------------------------------------------------------------------------
// Persistent fp16 mma.sync GCN layer. grid = 148, block = 512.
// CTA pinned to nh = blockIdx&1; loops over b = slot + i*74.
// B resident in smem; A streamed via 3-buffer cp.async pipeline, 2 chunks
// ahead ACROSS tile boundaries. All tiles + stage XOR-swizzled.
// Intermediate epilogue: vectorized 8B roll loop (swizzle keeps 8B blocks
// contiguous since 8*np mod 16 is always 0 or 8).
// ---------------------------------------------------------------------------
__global__ void __launch_bounds__(512, 1) k_mma(
    const __half* __restrict__ A, const __half* __restrict__ B,
    const float* __restrict__ bias,
    __half* __restrict__ O, float* __restrict__ out, int is_final) {
    extern __shared__ __align__(1024) char smc[];
    const uint32_t smb = s2u(smc);
    const int tid = threadIdx.x, wid = tid >> 5, lane = tid & 31;
    const int nh = blockIdx.x & 1, slot = blockIdx.x >> 1;
    const int wm = wid >> 2, wn = wid & 3;

    const uint32_t OFF_B = 98304u, OFF_S = 163840u;

    const __half* Bgl = B + nh * 32768;

    const int nt = (1024 - slot + 73) / 74;
    const int NC = 4 * nt;

    const int ar = tid >> 3, ac = tid & 7;
    const uint32_t swcA = (uint32_t)((ac * 16) ^ ((ar & 7) << 4));

#define ISSUE_A(BIDX, CH, BUF)                                               \
    do {                                                                     \
        const __half* _Ag = A + (size_t)(BIDX) * 65536;                      \
        uint32_t _dst = smb + (uint32_t)(BUF) * 32768u;                      \
        _Pragma("unroll") for (int _j = 0; _j < 4; _j++) {                   \
            int _row = ar + _j * 64;                                         \
            CP_ASYNC16(_dst + _row * 128 + swcA,                             \
                       _Ag + _row * 256 + (CH) * 64 + ac * 8);               \
        }                                                                    \
    } while (0)

#pragma unroll
    for (int j = 0; j < 8; j++) {
        int idx = tid + j * 512;
        int cS = idx >> 10, row = (idx >> 3) & 127, acb = idx & 7;
        uint32_t swc = (uint32_t)((acb * 16) ^ ((row & 7) << 4));
        CP_ASYNC16(smb + OFF_B + cS * 16384 + row * 128 + swc,
                   Bgl + row * 256 + cS * 64 + acb * 8);
    }
    ISSUE_A(slot, 0, 0);
    CP_COMMIT();
    ISSUE_A(slot, 1, 1);
    CP_COMMIT();

    const int li = lane >> 3, lr = lane & 7;
    uint32_t colk[4];
#pragma unroll
    for (int kt = 0; kt < 4; kt++)
        colk[kt] = (uint32_t)((kt * 32 + (li >> 1) * 16) ^ (lr << 4));
    const uint32_t aRow = smb + (uint32_t)(wm * 64 + (li & 1) * 8 + lr) * 128;
    const uint32_t bRow = smb + OFF_B + (uint32_t)(wn * 32 + (li & 1) * 8 + lr) * 128;

    const int r = lane >> 2, l2 = (lane & 3) * 2;
    float bj[4][2];
#pragma unroll
    for (int nt2 = 0; nt2 < 4; nt2++) {
        int n = nh * 128 + wn * 32 + nt2 * 8 + l2;
        bj[nt2][0] = bias[n];
        bj[nt2][1] = bias[n + 1];
    }

    int g = 0;
    for (int i = 0; i < nt; i++) {
        const int b = slot + i * SLOTS;

        float acc[4][4][4];
#pragma unroll
        for (int mt = 0; mt < 4; mt++)
#pragma unroll
            for (int nt2 = 0; nt2 < 4; nt2++)
#pragma unroll
                for (int q = 0; q < 4; q++) acc[mt][nt2][q] = 0.0f;

        for (int c = 0; c < 4; c++) {
            CP_WAIT(1);
            __syncthreads();
            int gn = g + 2;
            if (gn < NC) ISSUE_A(slot + (gn >> 2) * SLOTS, gn & 3, gn % 3);
            CP_COMMIT();

            const uint32_t aB = aRow + (uint32_t)(g % 3) * 32768u;
            const uint32_t bB = bRow + (uint32_t)c * 16384u;
#pragma unroll
            for (int kt = 0; kt < 4; kt++) {
                uint32_t ah[4][4];
#pragma unroll
                for (int mt = 0; mt < 4; mt++)
                    ldsm4(ah[mt][0], ah[mt][1], ah[mt][2], ah[mt][3],
                          aB + mt * 2048 + colk[kt]);
#pragma unroll
                for (int p = 0; p < 2; p++) {
                    uint32_t bh[4];
                    ldsm4(bh[0], bh[1], bh[2], bh[3], bB + p * 2048 + colk[kt]);
#pragma unroll
                    for (int mt = 0; mt < 4; mt++)
#pragma unroll
                        for (int s = 0; s < 2; s++)
                            mma16816(acc[mt][p * 2 + s], ah[mt], bh[s], bh[2 + s]);
                }
            }
            g++;
        }

        if (!is_final) {
#pragma unroll
            for (int mt = 0; mt < 4; mt++)
#pragma unroll
                for (int nt2 = 0; nt2 < 4; nt2++) {
                    int v = wm * 64 + mt * 16 + r;
                    uint32_t scol = (uint32_t)(((wn * 32 + nt2 * 8 + l2) * 2) ^ (r << 4));
                    *(__half2*)(smc + OFF_S + v * 256 + scol) = __floats2half2_rn(
                        fsilu(acc[mt][nt2][0] + bj[nt2][0]),
                        fsilu(acc[mt][nt2][1] + bj[nt2][1]));
                    *(__half2*)(smc + OFF_S + (v + 8) * 256 + scol) = __floats2half2_rn(
                        fsilu(acc[mt][nt2][2] + bj[nt2][0]),
                        fsilu(acc[mt][nt2][3] + bj[nt2][1]));
                }
            __syncthreads();
            // vectorized roll: each thread handles 4 cols (one uint2 = 2 half2)
            int np = tid & 31, vgE = tid >> 5;   // 32 col-quads x 16 v-groups
            __half* Og = O + (size_t)b * 65536 + nh * 128 + 4 * np;
            const __half2 third = __floats2half2_rn(1.0f / 3.0f, 1.0f / 3.0f);
#pragma unroll 4
            for (int v = vgE * 16; v < vgE * 16 + 16; v++) {
                int vm = (v + 255) & 255, vp = (v + 1) & 255;
                uint2 ua = *(const uint2*)(smc + OFF_S + vm * 256 +
                                           ((8 * np) ^ ((vm & 7) << 4)));
                uint2 ub = *(const uint2*)(smc + OFF_S + v * 256 +
                                           ((8 * np) ^ ((v & 7) << 4)));
                uint2 uc = *(const uint2*)(smc + OFF_S + vp * 256 +
                                           ((8 * np) ^ ((vp & 7) << 4)));
                __half2 r0 = __hmul2(__hadd2(__hadd2(*(__half2*)&ua.x,
                                                     *(__half2*)&ub.x),
                                             *(__half2*)&uc.x), third);
                __half2 r1 = __hmul2(__hadd2(__hadd2(*(__half2*)&ua.y,
                                                     *(__half2*)&ub.y),
                                             *(__half2*)&uc.y), third);
                uint2 res;
                res.x = *(uint32_t*)&r0;
                res.y = *(uint32_t*)&r1;
                *(uint2*)(Og + (size_t)v * 256) = res;
            }
            __syncthreads();
        } else {
            float cs[4][2];
#pragma unroll
            for (int nt2 = 0; nt2 < 4; nt2++) { cs[nt2][0] = 0.0f; cs[nt2][1] = 0.0f; }
#pragma unroll
            for (int mt = 0; mt < 4; mt++)
#pragma unroll
                for (int nt2 = 0; nt2 < 4; nt2++) {
                    cs[nt2][0] += fsilu(acc[mt][nt2][0] + bj[nt2][0]) +
                                  fsilu(acc[mt][nt2][2] + bj[nt2][0]);
                    cs[nt2][1] += fsilu(acc[mt][nt2][1] + bj[nt2][1]) +
                                  fsilu(acc[mt][nt2][3] + bj[nt2][1]);
                }
#pragma unroll
            for (int off = 4; off <= 16; off <<= 1)
#pragma unroll
                for (int nt2 = 0; nt2 < 4; nt2++) {
                    cs[nt2][0] += __shfl_xor_sync(0xFFFFFFFFu, cs[nt2][0], off);
                    cs[nt2][1] += __shfl_xor_sync(0xFFFFFFFFu, cs[nt2][1], off);
                }
            float* red = (float*)(smc + OFF_S);
            if (r == 0) {
#pragma unroll
                for (int nt2 = 0; nt2 < 4; nt2++) {
                    int n = wn * 32 + nt2 * 8 + l2;
                    red[wm * 128 + n]     = cs[nt2][0];
                    red[wm * 128 + n + 1] = cs[nt2][1];
                }
            }
            __syncthreads();
            if (tid < 128)
                out[b * 256 + nh * 128 + tid] =
                    (red[tid] + red[128 + tid] + red[256 + tid] + red[384 + tid]) *
                    (1.0f / 256.0f);
            __syncthreads();
        }
    }
    CP_WAIT(0);
}

// ---------------------------------------------------------------------------
extern "C" void kernel_launch(void* const* d_in, const int* in_sizes, int n_in,
                              void* d_out, int out_size) {
    const float* x  = (const float*)d_in[0];
    const float* t  = (const float*)d_in[1];
    const float* tw = (const float*)d_in[2];
    const float* tb = (const float*)d_in[3];
    const float* W0 = (const float*)d_in[4];
    const float* b0 = (const float*)d_in[5];
    const float* W1 = (const float*)d_in[6];
    const float* b1 = (const float*)d_in[7];
    const float* W2 = (const float*)d_in[8];
    const float* b2 = (const float*)d_in[9];
    float* out = (float*)d_out;

    cudaFuncSetAttribute(k_mma, cudaFuncAttributeMaxDynamicSharedMemorySize, 229376);

    __half *h1, *h2, *w;
    cudaGetSymbolAddress((void**)&h1, g_h1);
    cudaGetSymbolAddress((void**)&h2, g_h2);
    cudaGetSymbolAddress((void**)&w,  g_W);

    k_wconv<<<512, 256>>>(W1, W2);
    k_temb<<<BSZ, 128>>>(t, tw, tb, W0, b0);
    k_pew<<<256, 256>>>(W0);
    k_layer0<<<BSZ * 8, 256>>>(x, W0);
    k_mma<<<148, 512, 229376>>>(h1, w, b1, h2, nullptr, 0);
    k_mma<<<148, 512, 229376>>>(h2, w + 65536, b2, nullptr, out, 1);
}

// round 12
// speedup vs baseline: 1.1985x; 1.0153x over previous
#include <cuda_runtime.h>
#include <cuda_fp16.h>
#include <math.h>
#include <stdint.h>

#define BSZ 1024
#define SLOTS 74   // 148-CTA persistent grid, 74 slots per N-half

// ---------------------------------------------------------------------------
// Global scratch (static __device__ arrays, allocation-free)
// ---------------------------------------------------------------------------
__device__ float g_ctb[BSZ * 256];              // b0 + temb @ W0[6:134]
__device__ __half g_peWsh[256 * 256];           // roll-averaged pe @ W0[2:6], fp16
__device__ __half g_h1[(size_t)BSZ * 256 * 256];
__device__ __half g_h2[(size_t)BSZ * 256 * 256];
__device__ __half g_W[2 * 256 * 256];           // W^T fp16, [l][n][k]

// ---------------------------------------------------------------------------
// PTX helpers (sm_75/80-era: valid on the harness's sm_103 target)
// ---------------------------------------------------------------------------
__device__ __forceinline__ uint32_t s2u(const void* p) {
    uint32_t a;
    asm("{ .reg .u64 t; cvta.to.shared.u64 t, %1; cvt.u32.u64 %0, t; }"
        : "=r"(a) : "l"(p));
    return a;
}
#define CP_ASYNC16(dst, src) \
    asm volatile("cp.async.cg.shared.global [%0], [%1], 16;" :: "r"(dst), "l"(src))
#define CP_COMMIT() asm volatile("cp.async.commit_group;" ::: "memory")
#define CP_WAIT(n)  asm volatile("cp.async.wait_group %0;" :: "n"(n) : "memory")

__device__ __forceinline__ void ldsm4(uint32_t& r0, uint32_t& r1, uint32_t& r2,
                                      uint32_t& r3, uint32_t a) {
    asm volatile("ldmatrix.sync.aligned.m8n8.x4.shared.b16 {%0,%1,%2,%3}, [%4];"
                 : "=r"(r0), "=r"(r1), "=r"(r2), "=r"(r3) : "r"(a));
}
__device__ __forceinline__ void mma16816(float* d, const uint32_t* a,
                                         uint32_t b0, uint32_t b1) {
    asm volatile(
        "mma.sync.aligned.m16n8k16.row.col.f32.f16.f16.f32 "
        "{%0,%1,%2,%3}, {%4,%5,%6,%7}, {%8,%9}, {%0,%1,%2,%3};"
        : "+f"(d[0]), "+f"(d[1]), "+f"(d[2]), "+f"(d[3])
        : "r"(a[0]), "r"(a[1]), "r"(a[2]), "r"(a[3]), "r"(b0), "r"(b1));
}
// silu via single-MUFU tanh.approx: x*sigmoid(x) = 0.5x*tanh(0.5x) + 0.5x
__device__ __forceinline__ float fsilu(float x) {
    float t, h = 0.5f * x;
    asm("tanh.approx.f32 %0, %1;" : "=f"(t) : "f"(h));
    return fmaf(h, t, h);
}

// ---------------------------------------------------------------------------
// Kernel: weights -> fp16, transposed to [n][k]
// ---------------------------------------------------------------------------
__global__ void k_wconv(const float* __restrict__ W1, const float* __restrict__ W2) {
    int bb = blockIdx.x;           // 0..511
    int l = bb >> 8, k = bb & 255;
    int n = threadIdx.x;           // 0..255
    const float* W = l ? W2 : W1;
    g_W[l * 65536 + n * 256 + k] = __float2half(W[k * 256 + n]);
}

// ---------------------------------------------------------------------------
// Kernel: time embedding -> ctb = b0 + silu(sin-emb @ time_w + time_b) @ W0[6:]
// ---------------------------------------------------------------------------
__global__ void k_temb(const float* __restrict__ t, const float* __restrict__ tw,
                       const float* __restrict__ tb, const float* __restrict__ W0,
                       const float* __restrict__ b0) {
    __shared__ float emb[128];
    __shared__ float te[128];
    int b = blockIdx.x, tid = threadIdx.x;
    if (tid < 64) {
        float fr = expf(-9.210340371976184f * (float)tid / 63.0f);
        float a = t[b] * fr;
        emb[tid]      = sinf(a);
        emb[tid + 64] = cosf(a);
    }
    __syncthreads();
    float acc = tb[tid];
#pragma unroll 8
    for (int i = 0; i < 128; i++) acc += emb[i] * tw[i * 128 + tid];
    te[tid] = acc / (1.0f + expf(-acc));
    __syncthreads();
    for (int j = tid; j < 256; j += 128) {
        float a2 = b0[j];
#pragma unroll 8
        for (int k = 0; k < 128; k++) a2 += te[k] * W0[(6 + k) * 256 + j];
        g_ctb[b * 256 + j] = a2;
    }
}

// ---------------------------------------------------------------------------
// Kernel: peWs[v][j] = roll-avg(pe) @ W0[2:6] (roll factors folded in), fp16
// ---------------------------------------------------------------------------
__global__ void k_pew(const float* __restrict__ W0) {
    int v = blockIdx.x, j = threadIdx.x;
    const float dth = 6.283185307179586f / 256.0f;
    float f1 = (1.0f + 2.0f * cosf(dth)) / 3.0f;
    float f2 = (1.0f + 2.0f * cosf(2.0f * dth)) / 3.0f;
    float th = dth * (float)v;
    float s1 = sinf(th), c1 = cosf(th);
    float s2 = sinf(2.0f * th), c2 = cosf(2.0f * th);
    g_peWsh[v * 256 + j] =
        __float2half(f1 * (s1 * W0[2 * 256 + j] + c1 * W0[3 * 256 + j]) +
                     f2 * (s2 * W0[4 * 256 + j] + c2 * W0[5 * 256 + j]));
}

// ---------------------------------------------------------------------------
// Kernel: layer 0 collapsed, fp32 math + f32 tanh, peW rows prefetched to
// smem via cp.async. v-QUARTER split (validated R9 config: 38.3 us).
// grid = 4096 (b, v-quarter), block = 256 (128 col-pairs x 2 v-groups of 32).
// ---------------------------------------------------------------------------
__global__ void __launch_bounds__(256) k_layer0(const float* __restrict__ x,
                                                const float* __restrict__ W0) {
    __shared__ float xs[512];
    __shared__ float xa[256], ya[256];
    __shared__ __half pws[66 * 256];   // rows v0-1 .. v0+64 of peWsh (33 KB)
    int b = blockIdx.x >> 2, vq = blockIdx.x & 3;
    int tid = threadIdx.x;
    int v0q = vq * 64;

    // prefetch peW rows (wrap-around source rows -> linear smem rows)
    {
        uint32_t pb = s2u(pws);
        const char* src = (const char*)g_peWsh;
        int base = (v0q + 255) & 255;
#pragma unroll
        for (int i = tid; i < 66 * 32; i += 256) {
            int row = i >> 5, seg = i & 31;
            int vsrc = (base + row) & 255;
            CP_ASYNC16(pb + row * 512 + seg * 16, src + vsrc * 512 + seg * 16);
        }
        CP_COMMIT();
    }

    for (int i = tid; i < 512; i += 256) xs[i] = x[b * 512 + i];
    __syncthreads();
    {
        int v = tid, vm = (v + 255) & 255, vp = (v + 1) & 255;
        xa[v] = (xs[2 * vm] + xs[2 * v] + xs[2 * vp]) * (1.0f / 3.0f);
        ya[v] = (xs[2 * vm + 1] + xs[2 * v + 1] + xs[2 * vp + 1]) * (1.0f / 3.0f);
    }
    CP_WAIT(0);
    __syncthreads();

    int cp = tid & 127, vg = tid >> 7, c0 = 2 * cp;
    float w00 = W0[c0], w01 = W0[c0 + 1];
    float w10 = W0[256 + c0], w11 = W0[256 + c0 + 1];
    float cb0 = g_ctb[b * 256 + c0], cb1 = g_ctb[b * 256 + c0 + 1];
    int j0 = vg * 32 + 1;   // local row of first output v

#define HEVAL(JJ, H0, H1)                                                  \
    do {                                                                   \
        int _j = (JJ);                                                     \
        float2 pw = __half22float2(*(const __half2*)(pws + _j * 256 + c0));\
        int _v = (v0q + _j - 1) & 255;                                     \
        float _xv = xa[_v], _yv = ya[_v];                                  \
        float a0 = fmaf(_xv, w00, fmaf(_yv, w10, pw.x + cb0));             \
        float a1 = fmaf(_xv, w01, fmaf(_yv, w11, pw.y + cb1));             \
        H0 = fsilu(a0); H1 = fsilu(a1);                                    \
    } while (0)

    float hm0, hm1, hc0, hc1;
    HEVAL(j0 - 1, hm0, hm1);
    HEVAL(j0, hc0, hc1);
    __half* Og = g_h1 + (size_t)b * 65536 + (size_t)(v0q + vg * 32) * 256 + c0;
#pragma unroll 8
    for (int j = j0; j < j0 + 32; j++) {
        float hp0, hp1;
        HEVAL(j + 1, hp0, hp1);
        float t0 = (hm0 + hc0 + hp0) * (1.0f / 3.0f);
        float t1 = (hm1 + hc1 + hp1) * (1.0f / 3.0f);
        *(__half2*)Og = __floats2half2_rn(t0, t1);
        Og += 256;
        hm0 = hc0; hm1 = hc1; hc0 = hp0; hc1 = hp1;
    }
#undef HEVAL
}

// ---------------------------------------------------------------------------
// Persistent fp16 mma.sync GCN layer. grid = 148, block = 512.
// CTA pinned to nh = blockIdx&1; loops over b = slot + i*74.
// B resident in smem; A streamed via 3-buffer cp.async pipeline, 2 chunks
// ahead ACROSS tile boundaries. All tiles + stage XOR-swizzled.
// Intermediate epilogue: vectorized 8B roll loop (swizzle keeps 8B blocks
// contiguous since 8*np mod 16 is always 0 or 8).
// ---------------------------------------------------------------------------
__global__ void __launch_bounds__(512, 1) k_mma(
    const __half* __restrict__ A, const __half* __restrict__ B,
    const float* __restrict__ bias,
    __half* __restrict__ O, float* __restrict__ out, int is_final) {
    extern __shared__ __align__(1024) char smc[];
    const uint32_t smb = s2u(smc);
    const int tid = threadIdx.x, wid = tid >> 5, lane = tid & 31;
    const int nh = blockIdx.x & 1, slot = blockIdx.x >> 1;
    const int wm = wid >> 2, wn = wid & 3;

    const uint32_t OFF_B = 98304u, OFF_S = 163840u;

    const __half* Bgl = B + nh * 32768;

    const int nt = (1024 - slot + 73) / 74;
    const int NC = 4 * nt;

    const int ar = tid >> 3, ac = tid & 7;
    const uint32_t swcA = (uint32_t)((ac * 16) ^ ((ar & 7) << 4));

#define ISSUE_A(BIDX, CH, BUF)                                               \
    do {                                                                     \
        const __half* _Ag = A + (size_t)(BIDX) * 65536;                      \
        uint32_t _dst = smb + (uint32_t)(BUF) * 32768u;                      \
        _Pragma("unroll") for (int _j = 0; _j < 4; _j++) {                   \
            int _row = ar + _j * 64;                                         \
            CP_ASYNC16(_dst + _row * 128 + swcA,                             \
                       _Ag + _row * 256 + (CH) * 64 + ac * 8);               \
        }                                                                    \
    } while (0)

#pragma unroll
    for (int j = 0; j < 8; j++) {
        int idx = tid + j * 512;
        int cS = idx >> 10, row = (idx >> 3) & 127, acb = idx & 7;
        uint32_t swc = (uint32_t)((acb * 16) ^ ((row & 7) << 4));
        CP_ASYNC16(smb + OFF_B + cS * 16384 + row * 128 + swc,
                   Bgl + row * 256 + cS * 64 + acb * 8);
    }
    ISSUE_A(slot, 0, 0);
    CP_COMMIT();
    ISSUE_A(slot, 1, 1);
    CP_COMMIT();

    const int li = lane >> 3, lr = lane & 7;
    uint32_t colk[4];
#pragma unroll
    for (int kt = 0; kt < 4; kt++)
        colk[kt] = (uint32_t)((kt * 32 + (li >> 1) * 16) ^ (lr << 4));
    const uint32_t aRow = smb + (uint32_t)(wm * 64 + (li & 1) * 8 + lr) * 128;
    const uint32_t bRow = smb + OFF_B + (uint32_t)(wn * 32 + (li & 1) * 8 + lr) * 128;

    const int r = lane >> 2, l2 = (lane & 3) * 2;
    float bj[4][2];
#pragma unroll
    for (int nt2 = 0; nt2 < 4; nt2++) {
        int n = nh * 128 + wn * 32 + nt2 * 8 + l2;
        bj[nt2][0] = bias[n];
        bj[nt2][1] = bias[n + 1];
    }

    int g = 0;
    for (int i = 0; i < nt; i++) {
        const int b = slot + i * SLOTS;

        float acc[4][4][4];
#pragma unroll
        for (int mt = 0; mt < 4; mt++)
#pragma unroll
            for (int nt2 = 0; nt2 < 4; nt2++)
#pragma unroll
                for (int q = 0; q < 4; q++) acc[mt][nt2][q] = 0.0f;

        for (int c = 0; c < 4; c++) {
            CP_WAIT(1);
            __syncthreads();
            int gn = g + 2;
            if (gn < NC) ISSUE_A(slot + (gn >> 2) * SLOTS, gn & 3, gn % 3);
            CP_COMMIT();

            const uint32_t aB = aRow + (uint32_t)(g % 3) * 32768u;
            const uint32_t bB = bRow + (uint32_t)c * 16384u;
#pragma unroll
            for (int kt = 0; kt < 4; kt++) {
                uint32_t ah[4][4];
#pragma unroll
                for (int mt = 0; mt < 4; mt++)
                    ldsm4(ah[mt][0], ah[mt][1], ah[mt][2], ah[mt][3],
                          aB + mt * 2048 + colk[kt]);
#pragma unroll
                for (int p = 0; p < 2; p++) {
                    uint32_t bh[4];
                    ldsm4(bh[0], bh[1], bh[2], bh[3], bB + p * 2048 + colk[kt]);
#pragma unroll
                    for (int mt = 0; mt < 4; mt++)
#pragma unroll
                        for (int s = 0; s < 2; s++)
                            mma16816(acc[mt][p * 2 + s], ah[mt], bh[s], bh[2 + s]);
                }
            }
            g++;
        }

        if (!is_final) {
#pragma unroll
            for (int mt = 0; mt < 4; mt++)
#pragma unroll
                for (int nt2 = 0; nt2 < 4; nt2++) {
                    int v = wm * 64 + mt * 16 + r;
                    uint32_t scol = (uint32_t)(((wn * 32 + nt2 * 8 + l2) * 2) ^ (r << 4));
                    *(__half2*)(smc + OFF_S + v * 256 + scol) = __floats2half2_rn(
                        fsilu(acc[mt][nt2][0] + bj[nt2][0]),
                        fsilu(acc[mt][nt2][1] + bj[nt2][1]));
                    *(__half2*)(smc + OFF_S + (v + 8) * 256 + scol) = __floats2half2_rn(
                        fsilu(acc[mt][nt2][2] + bj[nt2][0]),
                        fsilu(acc[mt][nt2][3] + bj[nt2][1]));
                }
            __syncthreads();
            // vectorized roll: each thread handles 4 cols (one uint2 = 2 half2)
            int np = tid & 31, vgE = tid >> 5;   // 32 col-quads x 16 v-groups
            __half* Og = O + (size_t)b * 65536 + nh * 128 + 4 * np;
            const __half2 third = __floats2half2_rn(1.0f / 3.0f, 1.0f / 3.0f);
#pragma unroll 4
            for (int v = vgE * 16; v < vgE * 16 + 16; v++) {
                int vm = (v + 255) & 255, vp = (v + 1) & 255;
                uint2 ua = *(const uint2*)(smc + OFF_S + vm * 256 +
                                           ((8 * np) ^ ((vm & 7) << 4)));
                uint2 ub = *(const uint2*)(smc + OFF_S + v * 256 +
                                           ((8 * np) ^ ((v & 7) << 4)));
                uint2 uc = *(const uint2*)(smc + OFF_S + vp * 256 +
                                           ((8 * np) ^ ((vp & 7) << 4)));
                __half2 r0 = __hmul2(__hadd2(__hadd2(*(__half2*)&ua.x,
                                                     *(__half2*)&ub.x),
                                             *(__half2*)&uc.x), third);
                __half2 r1 = __hmul2(__hadd2(__hadd2(*(__half2*)&ua.y,
                                                     *(__half2*)&ub.y),
                                             *(__half2*)&uc.y), third);
                uint2 res;
                res.x = *(uint32_t*)&r0;
                res.y = *(uint32_t*)&r1;
                *(uint2*)(Og + (size_t)v * 256) = res;
            }
            __syncthreads();
        } else {
            float cs[4][2];
#pragma unroll
            for (int nt2 = 0; nt2 < 4; nt2++) { cs[nt2][0] = 0.0f; cs[nt2][1] = 0.0f; }
#pragma unroll
            for (int mt = 0; mt < 4; mt++)
#pragma unroll
                for (int nt2 = 0; nt2 < 4; nt2++) {
                    cs[nt2][0] += fsilu(acc[mt][nt2][0] + bj[nt2][0]) +
                                  fsilu(acc[mt][nt2][2] + bj[nt2][0]);
                    cs[nt2][1] += fsilu(acc[mt][nt2][1] + bj[nt2][1]) +
                                  fsilu(acc[mt][nt2][3] + bj[nt2][1]);
                }
#pragma unroll
            for (int off = 4; off <= 16; off <<= 1)
#pragma unroll
                for (int nt2 = 0; nt2 < 4; nt2++) {
                    cs[nt2][0] += __shfl_xor_sync(0xFFFFFFFFu, cs[nt2][0], off);
                    cs[nt2][1] += __shfl_xor_sync(0xFFFFFFFFu, cs[nt2][1], off);
                }
            float* red = (float*)(smc + OFF_S);
            if (r == 0) {
#pragma unroll
                for (int nt2 = 0; nt2 < 4; nt2++) {
                    int n = wn * 32 + nt2 * 8 + l2;
                    red[wm * 128 + n]     = cs[nt2][0];
                    red[wm * 128 + n + 1] = cs[nt2][1];
                }
            }
            __syncthreads();
            if (tid < 128)
                out[b * 256 + nh * 128 + tid] =
                    (red[tid] + red[128 + tid] + red[256 + tid] + red[384 + tid]) *
                    (1.0f / 256.0f);
            __syncthreads();
        }
    }
    CP_WAIT(0);
}

// ---------------------------------------------------------------------------
extern "C" void kernel_launch(void* const* d_in, const int* in_sizes, int n_in,
                              void* d_out, int out_size) {
    const float* x  = (const float*)d_in[0];
    const float* t  = (const float*)d_in[1];
    const float* tw = (const float*)d_in[2];
    const float* tb = (const float*)d_in[3];
    const float* W0 = (const float*)d_in[4];
    const float* b0 = (const float*)d_in[5];
    const float* W1 = (const float*)d_in[6];
    const float* b1 = (const float*)d_in[7];
    const float* W2 = (const float*)d_in[8];
    const float* b2 = (const float*)d_in[9];
    float* out = (float*)d_out;

    cudaFuncSetAttribute(k_mma, cudaFuncAttributeMaxDynamicSharedMemorySize, 229376);

    __half *h1, *h2, *w;
    cudaGetSymbolAddress((void**)&h1, g_h1);
    cudaGetSymbolAddress((void**)&h2, g_h2);
    cudaGetSymbolAddress((void**)&w,  g_W);

    k_wconv<<<512, 256>>>(W1, W2);
    k_temb<<<BSZ, 128>>>(t, tw, tb, W0, b0);
    k_pew<<<256, 256>>>(W0);
    k_layer0<<<BSZ * 4, 256>>>(x, W0);
    k_mma<<<148, 512, 229376>>>(h1, w, b1, h2, nullptr, 0);
    k_mma<<<148, 512, 229376>>>(h2, w + 65536, b2, nullptr, out, 1);
}

// round 13
// speedup vs baseline: 1.2440x; 1.0380x over previous
#include <cuda_runtime.h>
#include <cuda_fp16.h>
#include <math.h>
#include <stdint.h>

#define BSZ 1024
#define SLOTS 74   // 148-CTA persistent grid, 74 slots per N-half

// ---------------------------------------------------------------------------
// Global scratch (static __device__ arrays, allocation-free)
// ---------------------------------------------------------------------------
__device__ float g_ctb[BSZ * 256];              // b0 + temb @ W0[6:134]
__device__ __half g_peWsh[256 * 256];           // 0.5 * roll-avg(pe) @ W0[2:6]
__device__ __half g_h1[(size_t)BSZ * 256 * 256];
__device__ __half g_h2[(size_t)BSZ * 256 * 256];
__device__ __half g_W[2 * 256 * 256];           // W^T fp16, [l][n][k]
__device__ unsigned int g_bar;                  // monotonic global barrier ctr

// ---------------------------------------------------------------------------
// PTX helpers (sm_75/80-era: valid on the harness's sm_103 target)
// ---------------------------------------------------------------------------
__device__ __forceinline__ uint32_t s2u(const void* p) {
    uint32_t a;
    asm("{ .reg .u64 t; cvta.to.shared.u64 t, %1; cvt.u32.u64 %0, t; }"
        : "=r"(a) : "l"(p));
    return a;
}
#define CP_ASYNC16(dst, src) \
    asm volatile("cp.async.cg.shared.global [%0], [%1], 16;" :: "r"(dst), "l"(src))
#define CP_COMMIT() asm volatile("cp.async.commit_group;" ::: "memory")
#define CP_WAIT(n)  asm volatile("cp.async.wait_group %0;" :: "n"(n) : "memory")

__device__ __forceinline__ void ldsm4(uint32_t& r0, uint32_t& r1, uint32_t& r2,
                                      uint32_t& r3, uint32_t a) {
    asm volatile("ldmatrix.sync.aligned.m8n8.x4.shared.b16 {%0,%1,%2,%3}, [%4];"
                 : "=r"(r0), "=r"(r1), "=r"(r2), "=r"(r3) : "r"(a));
}
__device__ __forceinline__ void mma16816(float* d, const uint32_t* a,
                                         uint32_t b0, uint32_t b1) {
    asm volatile(
        "mma.sync.aligned.m16n8k16.row.col.f32.f16.f16.f32 "
        "{%0,%1,%2,%3}, {%4,%5,%6,%7}, {%8,%9}, {%0,%1,%2,%3};"
        : "+f"(d[0]), "+f"(d[1]), "+f"(d[2]), "+f"(d[3])
        : "r"(a[0]), "r"(a[1]), "r"(a[2]), "r"(a[3]), "r"(b0), "r"(b1));
}
// silu via single-MUFU tanh.approx: x*sigmoid(x) = 0.5x*tanh(0.5x) + 0.5x
__device__ __forceinline__ float fsilu(float x) {
    float t, h = 0.5f * x;
    asm("tanh.approx.f32 %0, %1;" : "=f"(t) : "f"(h));
    return fmaf(h, t, h);
}

// ---------------------------------------------------------------------------
// Kernel: merged prep. Blocks 0..511: weights -> fp16 transposed [n][k].
// Blocks 512..767: peWs[v][j] = 0.5 * roll-avg(pe) @ W0[2:6], fp16.
// ---------------------------------------------------------------------------
__global__ void __launch_bounds__(256) k_wpew(const float* __restrict__ W1,
                                              const float* __restrict__ W2,
                                              const float* __restrict__ W0) {
    int bb = blockIdx.x, tid = threadIdx.x;
    if (bb < 512) {
        int l = bb >> 8, k = bb & 255;
        const float* W = l ? W2 : W1;
        g_W[l * 65536 + tid * 256 + k] = __float2half(W[k * 256 + tid]);
        return;
    }
    int v = bb - 512, j = tid;
    const float dth = 6.283185307179586f / 256.0f;
    float f1 = (1.0f + 2.0f * cosf(dth)) / 3.0f;
    float f2 = (1.0f + 2.0f * cosf(2.0f * dth)) / 3.0f;
    float th = dth * (float)v;
    float s1 = sinf(th), c1 = cosf(th);
    float s2 = sinf(2.0f * th), c2 = cosf(2.0f * th);
    g_peWsh[v * 256 + j] = __float2half(
        0.5f * (f1 * (s1 * W0[2 * 256 + j] + c1 * W0[3 * 256 + j]) +
                f2 * (s2 * W0[4 * 256 + j] + c2 * W0[5 * 256 + j])));
}

// ---------------------------------------------------------------------------
// Kernel: time embedding -> ctb = b0 + silu(sin-emb @ time_w + time_b) @ W0[6:]
// ---------------------------------------------------------------------------
__global__ void k_temb(const float* __restrict__ t, const float* __restrict__ tw,
                       const float* __restrict__ tb, const float* __restrict__ W0,
                       const float* __restrict__ b0) {
    __shared__ float emb[128];
    __shared__ float te[128];
    int b = blockIdx.x, tid = threadIdx.x;
    if (tid < 64) {
        float fr = expf(-9.210340371976184f * (float)tid / 63.0f);
        float a = t[b] * fr;
        emb[tid]      = sinf(a);
        emb[tid + 64] = cosf(a);
    }
    __syncthreads();
    float acc = tb[tid];
#pragma unroll 8
    for (int i = 0; i < 128; i++) acc += emb[i] * tw[i * 128 + tid];
    te[tid] = acc / (1.0f + expf(-acc));
    __syncthreads();
    for (int j = tid; j < 256; j += 128) {
        float a2 = b0[j];
#pragma unroll 8
        for (int k = 0; k < 128; k++) a2 += te[k] * W0[(6 + k) * 256 + j];
        g_ctb[b * 256 + j] = a2;
    }
}

// ---------------------------------------------------------------------------
// Kernel: layer 0 collapsed. fp32 agg (accuracy) with the x0.5 silu factor
// folded into weights/ctb/peW table; silu tail + roll in half2 (one
// tanh.approx.f16x2 per TWO columns — matches k_mma's validated epilogue).
// grid = 4096 (b, v-quarter), block = 256 (128 col-pairs x 2 v-groups of 32).
// ---------------------------------------------------------------------------
__global__ void __launch_bounds__(256) k_layer0(const float* __restrict__ x,
                                                const float* __restrict__ W0) {
    __shared__ float xs[512];
    __shared__ float xa[256], ya[256];
    __shared__ __half pws[66 * 256];   // rows v0-1 .. v0+64 of peWsh (33 KB)
    int b = blockIdx.x >> 2, vq = blockIdx.x & 3;
    int tid = threadIdx.x;
    int v0q = vq * 64;

    // prefetch peW rows (wrap-around source rows -> linear smem rows)
    {
        uint32_t pb = s2u(pws);
        const char* src = (const char*)g_peWsh;
        int base = (v0q + 255) & 255;
#pragma unroll
        for (int i = tid; i < 66 * 32; i += 256) {
            int row = i >> 5, seg = i & 31;
            int vsrc = (base + row) & 255;
            CP_ASYNC16(pb + row * 512 + seg * 16, src + vsrc * 512 + seg * 16);
        }
        CP_COMMIT();
    }

    for (int i = tid; i < 512; i += 256) xs[i] = x[b * 512 + i];
    __syncthreads();
    {
        int v = tid, vm = (v + 255) & 255, vp = (v + 1) & 255;
        xa[v] = (xs[2 * vm] + xs[2 * v] + xs[2 * vp]) * (1.0f / 3.0f);
        ya[v] = (xs[2 * vm + 1] + xs[2 * v + 1] + xs[2 * vp + 1]) * (1.0f / 3.0f);
    }
    CP_WAIT(0);
    __syncthreads();

    int cp = tid & 127, vg = tid >> 7, c0 = 2 * cp;
    // 0.5 factor folded in (matches pre-scaled pws table)
    float w00 = 0.5f * W0[c0],       w01 = 0.5f * W0[c0 + 1];
    float w10 = 0.5f * W0[256 + c0], w11 = 0.5f * W0[256 + c0 + 1];
    float cb0 = 0.5f * g_ctb[b * 256 + c0], cb1 = 0.5f * g_ctb[b * 256 + c0 + 1];
    int j0 = vg * 32 + 1;   // local row of first output v
    const __half2 third = __floats2half2_rn(1.0f / 3.0f, 1.0f / 3.0f);

#define HEVAL(JJ, H)                                                        \
    do {                                                                    \
        int _j = (JJ);                                                      \
        float2 pw = __half22float2(*(const __half2*)(pws + _j * 256 + c0)); \
        int _v = (v0q + _j - 1) & 255;                                      \
        float _xv = xa[_v], _yv = ya[_v];                                   \
        float a0 = fmaf(_xv, w00, fmaf(_yv, w10, pw.x + cb0));              \
        float a1 = fmaf(_xv, w01, fmaf(_yv, w11, pw.y + cb1));              \
        __half2 _ha = __floats2half2_rn(a0, a1);                            \
        uint32_t _t, _hi = *(uint32_t*)&_ha;                                \
        asm("tanh.approx.f16x2 %0, %1;" : "=r"(_t) : "r"(_hi));             \
        H = __hfma2(_ha, *(__half2*)&_t, _ha);                              \
    } while (0)

    __half2 hm, hc;
    HEVAL(j0 - 1, hm);
    HEVAL(j0, hc);
    __half* Og = g_h1 + (size_t)b * 65536 + (size_t)(v0q + vg * 32) * 256 + c0;
#pragma unroll 8
    for (int j = j0; j < j0 + 32; j++) {
        __half2 hp;
        HEVAL(j + 1, hp);
        *(__half2*)Og = __hmul2(__hadd2(__hadd2(hm, hc), hp), third);
        Og += 256;
        hm = hc; hc = hp;
    }
#undef HEVAL
}

// ---------------------------------------------------------------------------
// MERGED persistent fp16 mma.sync kernel: layer1 + global barrier + layer2.
// grid = 148 (1 CTA/SM, all resident -> barrier-safe), block = 512.
// CTA pinned to nh; loops over b = slot + i*74, twice (lay 0 then lay 1).
// B resident per layer (W2 prefetched into the B region BEFORE the barrier,
// overlapping the barrier wait). A streamed via 3-buffer cp.async ring.
// Barrier: monotonic counter, phase = old/148 (graph-replay-safe, no reset).
// ---------------------------------------------------------------------------
__global__ void __launch_bounds__(512, 1) k_mma2(
    const __half* __restrict__ A1, const __half* __restrict__ W,
    const float* __restrict__ b1, const float* __restrict__ b2,
    __half* __restrict__ H2, float* __restrict__ out) {
    extern __shared__ __align__(1024) char smc[];
    const uint32_t smb = s2u(smc);
    const int tid = threadIdx.x, wid = tid >> 5, lane = tid & 31;
    const int nh = blockIdx.x & 1, slot = blockIdx.x >> 1;
    const int wm = wid >> 2, wn = wid & 3;

    const uint32_t OFF_B = 98304u, OFF_S = 163840u;

    const int nt = (1024 - slot + 73) / 74;

    const int ar = tid >> 3, ac = tid & 7;
    const uint32_t swcA = (uint32_t)((ac * 16) ^ ((ar & 7) << 4));

#define ISSUE_A(AGL, BIDX, CH, BUF)                                          \
    do {                                                                     \
        const __half* _Ag = (AGL) + (size_t)(BIDX) * 65536;                  \
        uint32_t _dst = smb + (uint32_t)(BUF) * 32768u;                      \
        _Pragma("unroll") for (int _j = 0; _j < 4; _j++) {                   \
            int _row = ar + _j * 64;                                         \
            CP_ASYNC16(_dst + _row * 128 + swcA,                             \
                       _Ag + _row * 256 + (CH) * 64 + ac * 8);               \
        }                                                                    \
    } while (0)

#define ISSUE_B(BGL)                                                         \
    do {                                                                     \
        _Pragma("unroll") for (int _j = 0; _j < 8; _j++) {                   \
            int _idx = tid + _j * 512;                                       \
            int _cS = _idx >> 10, _row = (_idx >> 3) & 127, _ab = _idx & 7;  \
            uint32_t _swc = (uint32_t)((_ab * 16) ^ ((_row & 7) << 4));      \
            CP_ASYNC16(smb + OFF_B + _cS * 16384 + _row * 128 + _swc,        \
                       (BGL) + _row * 256 + _cS * 64 + _ab * 8);             \
        }                                                                    \
    } while (0)

    const int li = lane >> 3, lr = lane & 7;
    uint32_t colk[4];
#pragma unroll
    for (int kt = 0; kt < 4; kt++)
        colk[kt] = (uint32_t)((kt * 32 + (li >> 1) * 16) ^ (lr << 4));
    const uint32_t aRow = smb + (uint32_t)(wm * 64 + (li & 1) * 8 + lr) * 128;
    const uint32_t bRow = smb + OFF_B + (uint32_t)(wn * 32 + (li & 1) * 8 + lr) * 128;
    const int r = lane >> 2, l2 = (lane & 3) * 2;

    // layer-0 prologue: B1 + A chunk 0 (group 0), A chunk 1 (group 1)
    ISSUE_B(W + nh * 32768);
    ISSUE_A(A1, slot, 0, 0);
    CP_COMMIT();
    ISSUE_A(A1, slot, 1, 1);
    CP_COMMIT();

    for (int lay = 0; lay < 2; lay++) {
        const __half* Agl = lay ? (const __half*)H2 : A1;
        const float* bias = lay ? b2 : b1;
        const int NC = 4 * nt;

        float bj[4][2];
#pragma unroll
        for (int nt2 = 0; nt2 < 4; nt2++) {
            int n = nh * 128 + wn * 32 + nt2 * 8 + l2;
            bj[nt2][0] = bias[n];
            bj[nt2][1] = bias[n + 1];
        }

        int g = 0;
        for (int i = 0; i < nt; i++) {
            const int b = slot + i * SLOTS;

            float acc[4][4][4];
#pragma unroll
            for (int mt = 0; mt < 4; mt++)
#pragma unroll
                for (int nt2 = 0; nt2 < 4; nt2++)
#pragma unroll
                    for (int q = 0; q < 4; q++) acc[mt][nt2][q] = 0.0f;

            for (int c = 0; c < 4; c++) {
                CP_WAIT(1);
                __syncthreads();
                int gn = g + 2;
                if (gn < NC) ISSUE_A(Agl, slot + (gn >> 2) * SLOTS, gn & 3, gn % 3);
                CP_COMMIT();

                const uint32_t aB = aRow + (uint32_t)(g % 3) * 32768u;
                const uint32_t bB = bRow + (uint32_t)c * 16384u;
#pragma unroll
                for (int kt = 0; kt < 4; kt++) {
                    uint32_t ah[4][4];
#pragma unroll
                    for (int mt = 0; mt < 4; mt++)
                        ldsm4(ah[mt][0], ah[mt][1], ah[mt][2], ah[mt][3],
                              aB + mt * 2048 + colk[kt]);
#pragma unroll
                    for (int p = 0; p < 2; p++) {
                        uint32_t bh[4];
                        ldsm4(bh[0], bh[1], bh[2], bh[3], bB + p * 2048 + colk[kt]);
#pragma unroll
                        for (int mt = 0; mt < 4; mt++)
#pragma unroll
                            for (int s = 0; s < 2; s++)
                                mma16816(acc[mt][p * 2 + s], ah[mt], bh[s], bh[2 + s]);
                    }
                }
                g++;
            }

            if (lay == 0) {
                // intermediate epilogue: silu -> swizzled half2 stage -> roll -> H2
#pragma unroll
                for (int mt = 0; mt < 4; mt++)
#pragma unroll
                    for (int nt2 = 0; nt2 < 4; nt2++) {
                        int v = wm * 64 + mt * 16 + r;
                        uint32_t scol =
                            (uint32_t)(((wn * 32 + nt2 * 8 + l2) * 2) ^ (r << 4));
                        *(__half2*)(smc + OFF_S + v * 256 + scol) = __floats2half2_rn(
                            fsilu(acc[mt][nt2][0] + bj[nt2][0]),
                            fsilu(acc[mt][nt2][1] + bj[nt2][1]));
                        *(__half2*)(smc + OFF_S + (v + 8) * 256 + scol) =
                            __floats2half2_rn(
                                fsilu(acc[mt][nt2][2] + bj[nt2][0]),
                                fsilu(acc[mt][nt2][3] + bj[nt2][1]));
                    }
                __syncthreads();
                int np = tid & 31, vgE = tid >> 5;
                __half* Og = H2 + (size_t)b * 65536 + nh * 128 + 4 * np;
                const __half2 third = __floats2half2_rn(1.0f / 3.0f, 1.0f / 3.0f);
#pragma unroll 4
                for (int v = vgE * 16; v < vgE * 16 + 16; v++) {
                    int vm = (v + 255) & 255, vp = (v + 1) & 255;
                    uint2 ua = *(const uint2*)(smc + OFF_S + vm * 256 +
                                               ((8 * np) ^ ((vm & 7) << 4)));
                    uint2 ub = *(const uint2*)(smc + OFF_S + v * 256 +
                                               ((8 * np) ^ ((v & 7) << 4)));
                    uint2 uc = *(const uint2*)(smc + OFF_S + vp * 256 +
                                               ((8 * np) ^ ((vp & 7) << 4)));
                    __half2 r0 = __hmul2(__hadd2(__hadd2(*(__half2*)&ua.x,
                                                         *(__half2*)&ub.x),
                                                 *(__half2*)&uc.x), third);
                    __half2 r1 = __hmul2(__hadd2(__hadd2(*(__half2*)&ua.y,
                                                         *(__half2*)&ub.y),
                                                 *(__half2*)&uc.y), third);
                    uint2 res;
                    res.x = *(uint32_t*)&r0;
                    res.y = *(uint32_t*)&r1;
                    *(uint2*)(Og + (size_t)v * 256) = res;
                }
                __syncthreads();
            } else {
                // final epilogue: silu in regs + mean pool, shfl + smem reduce
                float cs[4][2];
#pragma unroll
                for (int nt2 = 0; nt2 < 4; nt2++) { cs[nt2][0] = 0.0f; cs[nt2][1] = 0.0f; }
#pragma unroll
                for (int mt = 0; mt < 4; mt++)
#pragma unroll
                    for (int nt2 = 0; nt2 < 4; nt2++) {
                        cs[nt2][0] += fsilu(acc[mt][nt2][0] + bj[nt2][0]) +
                                      fsilu(acc[mt][nt2][2] + bj[nt2][0]);
                        cs[nt2][1] += fsilu(acc[mt][nt2][1] + bj[nt2][1]) +
                                      fsilu(acc[mt][nt2][3] + bj[nt2][1]);
                    }
#pragma unroll
                for (int off = 4; off <= 16; off <<= 1)
#pragma unroll
                    for (int nt2 = 0; nt2 < 4; nt2++) {
                        cs[nt2][0] += __shfl_xor_sync(0xFFFFFFFFu, cs[nt2][0], off);
                        cs[nt2][1] += __shfl_xor_sync(0xFFFFFFFFu, cs[nt2][1], off);
                    }
                float* red = (float*)(smc + OFF_S);
                if (r == 0) {
#pragma unroll
                    for (int nt2 = 0; nt2 < 4; nt2++) {
                        int n = wn * 32 + nt2 * 8 + l2;
                        red[wm * 128 + n]     = cs[nt2][0];
                        red[wm * 128 + n + 1] = cs[nt2][1];
                    }
                }
                __syncthreads();
                if (tid < 128)
                    out[b * 256 + nh * 128 + tid] =
                        (red[tid] + red[128 + tid] + red[256 + tid] + red[384 + tid]) *
                        (1.0f / 256.0f);
                __syncthreads();
            }
        }

        if (lay == 0) {
            CP_WAIT(0);          // drain layer-1 A pipeline
            __syncthreads();
            ISSUE_B(W + 65536 + nh * 32768);   // prefetch W2 (overlaps barrier)
            CP_COMMIT();
            __threadfence();     // release H2 stores
            __syncthreads();
            if (tid == 0) {
                unsigned int old = atomicAdd(&g_bar, 1u);
                unsigned int target = (old / 148u + 1u) * 148u;
                unsigned int cur;
                do {
                    asm volatile("ld.acquire.gpu.u32 %0, [%1];"
                                 : "=r"(cur) : "l"(&g_bar));
                    if (cur < target) __nanosleep(256);
                } while (cur < target);
            }
            __syncthreads();
            // prime layer-2 A pipeline (B2 already in flight as earlier group)
            ISSUE_A(H2, slot, 0, 0);
            CP_COMMIT();
            ISSUE_A(H2, slot, 1, 1);
            CP_COMMIT();
        }
    }
    CP_WAIT(0);
}

// ---------------------------------------------------------------------------
extern "C" void kernel_launch(void* const* d_in, const int* in_sizes, int n_in,
                              void* d_out, int out_size) {
    const float* x  = (const float*)d_in[0];
    const float* t  = (const float*)d_in[1];
    const float* tw = (const float*)d_in[2];
    const float* tb = (const float*)d_in[3];
    const float* W0 = (const float*)d_in[4];
    const float* b0 = (const float*)d_in[5];
    const float* W1 = (const float*)d_in[6];
    const float* b1 = (const float*)d_in[7];
    const float* W2 = (const float*)d_in[8];
    const float* b2 = (const float*)d_in[9];
    float* out = (float*)d_out;

    cudaFuncSetAttribute(k_mma2, cudaFuncAttributeMaxDynamicSharedMemorySize, 229376);

    __half *h1, *h2, *w;
    cudaGetSymbolAddress((void**)&h1, g_h1);
    cudaGetSymbolAddress((void**)&h2, g_h2);
    cudaGetSymbolAddress((void**)&w,  g_W);

    k_wpew<<<768, 256>>>(W1, W2, W0);
    k_temb<<<BSZ, 128>>>(t, tw, tb, W0, b0);
    k_layer0<<<BSZ * 4, 256>>>(x, W0);
    k_mma2<<<148, 512, 229376>>>(h1, w, b1, b2, h2, out);
}

// round 14
// speedup vs baseline: 1.2629x; 1.0151x over previous
#include <cuda_runtime.h>
#include <cuda_fp16.h>
#include <math.h>
#include <stdint.h>

#define BSZ 1024
#define SLOTS 74   // 148-CTA persistent grid, 74 slots per N-half

// ---------------------------------------------------------------------------
// Global scratch (static __device__ arrays, allocation-free)
// ---------------------------------------------------------------------------
__device__ float g_ctb[BSZ * 256];              // b0 + temb @ W0[6:134]
__device__ __half g_peWsh[256 * 256];           // roll-avg(pe) @ W0[2:6], fp16
__device__ __half g_h1[(size_t)BSZ * 256 * 256];
__device__ __half g_h2[(size_t)BSZ * 256 * 256];
__device__ __half g_W[2 * 256 * 256];           // W^T fp16, [l][n][k]
__device__ unsigned int g_bar;                  // monotonic global barrier ctr

// ---------------------------------------------------------------------------
// PTX helpers (sm_75/80-era: valid on the harness's sm_103 target)
// ---------------------------------------------------------------------------
__device__ __forceinline__ uint32_t s2u(const void* p) {
    uint32_t a;
    asm("{ .reg .u64 t; cvta.to.shared.u64 t, %1; cvt.u32.u64 %0, t; }"
        : "=r"(a) : "l"(p));
    return a;
}
#define CP_ASYNC16(dst, src) \
    asm volatile("cp.async.cg.shared.global [%0], [%1], 16;" :: "r"(dst), "l"(src))
#define CP_COMMIT() asm volatile("cp.async.commit_group;" ::: "memory")
#define CP_WAIT(n)  asm volatile("cp.async.wait_group %0;" :: "n"(n) : "memory")

__device__ __forceinline__ void ldsm4(uint32_t& r0, uint32_t& r1, uint32_t& r2,
                                      uint32_t& r3, uint32_t a) {
    asm volatile("ldmatrix.sync.aligned.m8n8.x4.shared.b16 {%0,%1,%2,%3}, [%4];"
                 : "=r"(r0), "=r"(r1), "=r"(r2), "=r"(r3) : "r"(a));
}
__device__ __forceinline__ void mma16816(float* d, const uint32_t* a,
                                         uint32_t b0, uint32_t b1) {
    asm volatile(
        "mma.sync.aligned.m16n8k16.row.col.f32.f16.f16.f32 "
        "{%0,%1,%2,%3}, {%4,%5,%6,%7}, {%8,%9}, {%0,%1,%2,%3};"
        : "+f"(d[0]), "+f"(d[1]), "+f"(d[2]), "+f"(d[3])
        : "r"(a[0]), "r"(a[1]), "r"(a[2]), "r"(a[3]), "r"(b0), "r"(b1));
}
// silu via single-MUFU tanh.approx: x*sigmoid(x) = 0.5x*tanh(0.5x) + 0.5x
__device__ __forceinline__ float fsilu(float x) {
    float t, h = 0.5f * x;
    asm("tanh.approx.f32 %0, %1;" : "=f"(t) : "f"(h));
    return fmaf(h, t, h);
}

// ---------------------------------------------------------------------------
// Kernel: merged prep.
//   blocks 0..511    : weights -> fp16 transposed [n][k]
//   blocks 512..767  : peWs[v][j] = roll-avg(pe) @ W0[2:6], fp16 (unscaled)
//   blocks 768..1791 : per-batch time embedding -> g_ctb
// ---------------------------------------------------------------------------
__global__ void __launch_bounds__(256) k_prep(
    const float* __restrict__ W1, const float* __restrict__ W2,
    const float* __restrict__ W0, const float* __restrict__ t,
    const float* __restrict__ tw, const float* __restrict__ tb,
    const float* __restrict__ b0) {
    int bb = blockIdx.x, tid = threadIdx.x;
    if (bb < 512) {
        int l = bb >> 8, k = bb & 255;
        const float* W = l ? W2 : W1;
        g_W[l * 65536 + tid * 256 + k] = __float2half(W[k * 256 + tid]);
        return;
    }
    if (bb < 768) {
        int v = bb - 512, j = tid;
        const float dth = 6.283185307179586f / 256.0f;
        float f1 = (1.0f + 2.0f * cosf(dth)) / 3.0f;
        float f2 = (1.0f + 2.0f * cosf(2.0f * dth)) / 3.0f;
        float th = dth * (float)v;
        float s1 = sinf(th), c1 = cosf(th);
        float s2 = sinf(2.0f * th), c2 = cosf(2.0f * th);
        g_peWsh[v * 256 + j] = __float2half(
            f1 * (s1 * W0[2 * 256 + j] + c1 * W0[3 * 256 + j]) +
            f2 * (s2 * W0[4 * 256 + j] + c2 * W0[5 * 256 + j]));
        return;
    }
    // time embedding
    int b = bb - 768;
    __shared__ float emb[128];
    __shared__ float te[128];
    if (tid < 64) {
        float fr = expf(-9.210340371976184f * (float)tid / 63.0f);
        float a = t[b] * fr;
        emb[tid]      = sinf(a);
        emb[tid + 64] = cosf(a);
    }
    __syncthreads();
    if (tid < 128) {
        float acc = tb[tid];
#pragma unroll 8
        for (int i = 0; i < 128; i++) acc += emb[i] * tw[i * 128 + tid];
        te[tid] = acc / (1.0f + expf(-acc));
    }
    __syncthreads();
    {
        float a2 = b0[tid];
#pragma unroll 8
        for (int k = 0; k < 128; k++) a2 += te[k] * W0[(6 + k) * 256 + tid];
        g_ctb[b * 256 + tid] = a2;
    }
}

// ---------------------------------------------------------------------------
// Kernel: layer 0 collapsed, fp32 math + f32 tanh (validated R12 config),
// peW rows prefetched to smem via cp.async.
// grid = 4096 (b, v-quarter), block = 256 (128 col-pairs x 2 v-groups of 32).
// ---------------------------------------------------------------------------
__global__ void __launch_bounds__(256) k_layer0(const float* __restrict__ x,
                                                const float* __restrict__ W0) {
    __shared__ float xs[512];
    __shared__ float xa[256], ya[256];
    __shared__ __half pws[66 * 256];   // rows v0-1 .. v0+64 of peWsh (33 KB)
    int b = blockIdx.x >> 2, vq = blockIdx.x & 3;
    int tid = threadIdx.x;
    int v0q = vq * 64;

    // prefetch peW rows (wrap-around source rows -> linear smem rows)
    {
        uint32_t pb = s2u(pws);
        const char* src = (const char*)g_peWsh;
        int base = (v0q + 255) & 255;
#pragma unroll
        for (int i = tid; i < 66 * 32; i += 256) {
            int row = i >> 5, seg = i & 31;
            int vsrc = (base + row) & 255;
            CP_ASYNC16(pb + row * 512 + seg * 16, src + vsrc * 512 + seg * 16);
        }
        CP_COMMIT();
    }

    for (int i = tid; i < 512; i += 256) xs[i] = x[b * 512 + i];
    __syncthreads();
    {
        int v = tid, vm = (v + 255) & 255, vp = (v + 1) & 255;
        xa[v] = (xs[2 * vm] + xs[2 * v] + xs[2 * vp]) * (1.0f / 3.0f);
        ya[v] = (xs[2 * vm + 1] + xs[2 * v + 1] + xs[2 * vp + 1]) * (1.0f / 3.0f);
    }
    CP_WAIT(0);
    __syncthreads();

    int cp = tid & 127, vg = tid >> 7, c0 = 2 * cp;
    float w00 = W0[c0], w01 = W0[c0 + 1];
    float w10 = W0[256 + c0], w11 = W0[256 + c0 + 1];
    float cb0 = g_ctb[b * 256 + c0], cb1 = g_ctb[b * 256 + c0 + 1];
    int j0 = vg * 32 + 1;   // local row of first output v

#define HEVAL(JJ, H0, H1)                                                  \
    do {                                                                   \
        int _j = (JJ);                                                     \
        float2 pw = __half22float2(*(const __half2*)(pws + _j * 256 + c0));\
        int _v = (v0q + _j - 1) & 255;                                     \
        float _xv = xa[_v], _yv = ya[_v];                                  \
        float a0 = fmaf(_xv, w00, fmaf(_yv, w10, pw.x + cb0));             \
        float a1 = fmaf(_xv, w01, fmaf(_yv, w11, pw.y + cb1));             \
        H0 = fsilu(a0); H1 = fsilu(a1);                                    \
    } while (0)

    float hm0, hm1, hc0, hc1;
    HEVAL(j0 - 1, hm0, hm1);
    HEVAL(j0, hc0, hc1);
    __half* Og = g_h1 + (size_t)b * 65536 + (size_t)(v0q + vg * 32) * 256 + c0;
#pragma unroll 8
    for (int j = j0; j < j0 + 32; j++) {
        float hp0, hp1;
        HEVAL(j + 1, hp0, hp1);
        float t0 = (hm0 + hc0 + hp0) * (1.0f / 3.0f);
        float t1 = (hm1 + hc1 + hp1) * (1.0f / 3.0f);
        *(__half2*)Og = __floats2half2_rn(t0, t1);
        Og += 256;
        hm0 = hc0; hm1 = hc1; hc0 = hp0; hc1 = hp1;
    }
#undef HEVAL
}

// ---------------------------------------------------------------------------
// MERGED persistent fp16 mma.sync kernel: layer1 + global barrier + layer2.
// grid = 148 (1 CTA/SM, all resident -> barrier-safe), block = 512.
// CTA pinned to nh; loops over b = slot + i*74, twice (lay 0 then lay 1).
// B resident per layer (W2 prefetched into the B region BEFORE the barrier,
// overlapping the barrier wait). A streamed via 3-buffer cp.async ring.
// Barrier: monotonic counter, phase = old/148 (graph-replay-safe, no reset).
// ---------------------------------------------------------------------------
__global__ void __launch_bounds__(512, 1) k_mma2(
    const __half* __restrict__ A1, const __half* __restrict__ W,
    const float* __restrict__ b1, const float* __restrict__ b2,
    __half* __restrict__ H2, float* __restrict__ out) {
    extern __shared__ __align__(1024) char smc[];
    const uint32_t smb = s2u(smc);
    const int tid = threadIdx.x, wid = tid >> 5, lane = tid & 31;
    const int nh = blockIdx.x & 1, slot = blockIdx.x >> 1;
    const int wm = wid >> 2, wn = wid & 3;

    const uint32_t OFF_B = 98304u, OFF_S = 163840u;

    const int nt = (1024 - slot + 73) / 74;

    const int ar = tid >> 3, ac = tid & 7;
    const uint32_t swcA = (uint32_t)((ac * 16) ^ ((ar & 7) << 4));

#define ISSUE_A(AGL, BIDX, CH, BUF)                                          \
    do {                                                                     \
        const __half* _Ag = (AGL) + (size_t)(BIDX) * 65536;                  \
        uint32_t _dst = smb + (uint32_t)(BUF) * 32768u;                      \
        _Pragma("unroll") for (int _j = 0; _j < 4; _j++) {                   \
            int _row = ar + _j * 64;                                         \
            CP_ASYNC16(_dst + _row * 128 + swcA,                             \
                       _Ag + _row * 256 + (CH) * 64 + ac * 8);               \
        }                                                                    \
    } while (0)

#define ISSUE_B(BGL)                                                         \
    do {                                                                     \
        _Pragma("unroll") for (int _j = 0; _j < 8; _j++) {                   \
            int _idx = tid + _j * 512;                                       \
            int _cS = _idx >> 10, _row = (_idx >> 3) & 127, _ab = _idx & 7;  \
            uint32_t _swc = (uint32_t)((_ab * 16) ^ ((_row & 7) << 4));      \
            CP_ASYNC16(smb + OFF_B + _cS * 16384 + _row * 128 + _swc,        \
                       (BGL) + _row * 256 + _cS * 64 + _ab * 8);             \
        }                                                                    \
    } while (0)

    const int li = lane >> 3, lr = lane & 7;
    uint32_t colk[4];
#pragma unroll
    for (int kt = 0; kt < 4; kt++)
        colk[kt] = (uint32_t)((kt * 32 + (li >> 1) * 16) ^ (lr << 4));
    const uint32_t aRow = smb + (uint32_t)(wm * 64 + (li & 1) * 8 + lr) * 128;
    const uint32_t bRow = smb + OFF_B + (uint32_t)(wn * 32 + (li & 1) * 8 + lr) * 128;
    const int r = lane >> 2, l2 = (lane & 3) * 2;

    // layer-0 prologue: B1 + A chunk 0 (group 0), A chunk 1 (group 1)
    ISSUE_B(W + nh * 32768);
    ISSUE_A(A1, slot, 0, 0);
    CP_COMMIT();
    ISSUE_A(A1, slot, 1, 1);
    CP_COMMIT();

    for (int lay = 0; lay < 2; lay++) {
        const __half* Agl = lay ? (const __half*)H2 : A1;
        const float* bias = lay ? b2 : b1;
        const int NC = 4 * nt;

        float bj[4][2];
#pragma unroll
        for (int nt2 = 0; nt2 < 4; nt2++) {
            int n = nh * 128 + wn * 32 + nt2 * 8 + l2;
            bj[nt2][0] = bias[n];
            bj[nt2][1] = bias[n + 1];
        }

        int g = 0;
        for (int i = 0; i < nt; i++) {
            const int b = slot + i * SLOTS;

            float acc[4][4][4];
#pragma unroll
            for (int mt = 0; mt < 4; mt++)
#pragma unroll
                for (int nt2 = 0; nt2 < 4; nt2++)
#pragma unroll
                    for (int q = 0; q < 4; q++) acc[mt][nt2][q] = 0.0f;

            for (int c = 0; c < 4; c++) {
                CP_WAIT(1);
                __syncthreads();
                int gn = g + 2;
                if (gn < NC) ISSUE_A(Agl, slot + (gn >> 2) * SLOTS, gn & 3, gn % 3);
                CP_COMMIT();

                const uint32_t aB = aRow + (uint32_t)(g % 3) * 32768u;
                const uint32_t bB = bRow + (uint32_t)c * 16384u;
#pragma unroll
                for (int kt = 0; kt < 4; kt++) {
                    uint32_t ah[4][4];
#pragma unroll
                    for (int mt = 0; mt < 4; mt++)
                        ldsm4(ah[mt][0], ah[mt][1], ah[mt][2], ah[mt][3],
                              aB + mt * 2048 + colk[kt]);
#pragma unroll
                    for (int p = 0; p < 2; p++) {
                        uint32_t bh[4];
                        ldsm4(bh[0], bh[1], bh[2], bh[3], bB + p * 2048 + colk[kt]);
#pragma unroll
                        for (int mt = 0; mt < 4; mt++)
#pragma unroll
                            for (int s = 0; s < 2; s++)
                                mma16816(acc[mt][p * 2 + s], ah[mt], bh[s], bh[2 + s]);
                    }
                }
                g++;
            }

            if (lay == 0) {
                // intermediate epilogue: silu -> swizzled half2 stage -> roll -> H2
#pragma unroll
                for (int mt = 0; mt < 4; mt++)
#pragma unroll
                    for (int nt2 = 0; nt2 < 4; nt2++) {
                        int v = wm * 64 + mt * 16 + r;
                        uint32_t scol =
                            (uint32_t)(((wn * 32 + nt2 * 8 + l2) * 2) ^ (r << 4));
                        *(__half2*)(smc + OFF_S + v * 256 + scol) = __floats2half2_rn(
                            fsilu(acc[mt][nt2][0] + bj[nt2][0]),
                            fsilu(acc[mt][nt2][1] + bj[nt2][1]));
                        *(__half2*)(smc + OFF_S + (v + 8) * 256 + scol) =
                            __floats2half2_rn(
                                fsilu(acc[mt][nt2][2] + bj[nt2][0]),
                                fsilu(acc[mt][nt2][3] + bj[nt2][1]));
                    }
                __syncthreads();
                int np = tid & 31, vgE = tid >> 5;
                __half* Og = H2 + (size_t)b * 65536 + nh * 128 + 4 * np;
                const __half2 third = __floats2half2_rn(1.0f / 3.0f, 1.0f / 3.0f);
#pragma unroll 4
                for (int v = vgE * 16; v < vgE * 16 + 16; v++) {
                    int vm = (v + 255) & 255, vp = (v + 1) & 255;
                    uint2 ua = *(const uint2*)(smc + OFF_S + vm * 256 +
                                               ((8 * np) ^ ((vm & 7) << 4)));
                    uint2 ub = *(const uint2*)(smc + OFF_S + v * 256 +
                                               ((8 * np) ^ ((v & 7) << 4)));
                    uint2 uc = *(const uint2*)(smc + OFF_S + vp * 256 +
                                               ((8 * np) ^ ((vp & 7) << 4)));
                    __half2 r0 = __hmul2(__hadd2(__hadd2(*(__half2*)&ua.x,
                                                         *(__half2*)&ub.x),
                                                 *(__half2*)&uc.x), third);
                    __half2 r1 = __hmul2(__hadd2(__hadd2(*(__half2*)&ua.y,
                                                         *(__half2*)&ub.y),
                                                 *(__half2*)&uc.y), third);
                    uint2 res;
                    res.x = *(uint32_t*)&r0;
                    res.y = *(uint32_t*)&r1;
                    *(uint2*)(Og + (size_t)v * 256) = res;
                }
                __syncthreads();
            } else {
                // final epilogue: silu in regs + mean pool, shfl + smem reduce
                float cs[4][2];
#pragma unroll
                for (int nt2 = 0; nt2 < 4; nt2++) { cs[nt2][0] = 0.0f; cs[nt2][1] = 0.0f; }
#pragma unroll
                for (int mt = 0; mt < 4; mt++)
#pragma unroll
                    for (int nt2 = 0; nt2 < 4; nt2++) {
                        cs[nt2][0] += fsilu(acc[mt][nt2][0] + bj[nt2][0]) +
                                      fsilu(acc[mt][nt2][2] + bj[nt2][0]);
                        cs[nt2][1] += fsilu(acc[mt][nt2][1] + bj[nt2][1]) +
                                      fsilu(acc[mt][nt2][3] + bj[nt2][1]);
                    }
#pragma unroll
                for (int off = 4; off <= 16; off <<= 1)
#pragma unroll
                    for (int nt2 = 0; nt2 < 4; nt2++) {
                        cs[nt2][0] += __shfl_xor_sync(0xFFFFFFFFu, cs[nt2][0], off);
                        cs[nt2][1] += __shfl_xor_sync(0xFFFFFFFFu, cs[nt2][1], off);
                    }
                float* red = (float*)(smc + OFF_S);
                if (r == 0) {
#pragma unroll
                    for (int nt2 = 0; nt2 < 4; nt2++) {
                        int n = wn * 32 + nt2 * 8 + l2;
                        red[wm * 128 + n]     = cs[nt2][0];
                        red[wm * 128 + n + 1] = cs[nt2][1];
                    }
                }
                __syncthreads();
                if (tid < 128)
                    out[b * 256 + nh * 128 + tid] =
                        (red[tid] + red[128 + tid] + red[256 + tid] + red[384 + tid]) *
                        (1.0f / 256.0f);
                __syncthreads();
            }
        }

        if (lay == 0) {
            CP_WAIT(0);          // drain layer-1 A pipeline
            __syncthreads();
            ISSUE_B(W + 65536 + nh * 32768);   // prefetch W2 (overlaps barrier)
            CP_COMMIT();
            __threadfence();     // release H2 stores
            __syncthreads();
            if (tid == 0) {
                unsigned int old = atomicAdd(&g_bar, 1u);
                unsigned int target = (old / 148u + 1u) * 148u;
                unsigned int cur;
                do {
                    asm volatile("ld.acquire.gpu.u32 %0, [%1];"
                                 : "=r"(cur) : "l"(&g_bar));
                    if (cur < target) __nanosleep(256);
                } while (cur < target);
            }
            __syncthreads();
            // prime layer-2 A pipeline (B2 already in flight as earlier group)
            ISSUE_A(H2, slot, 0, 0);
            CP_COMMIT();
            ISSUE_A(H2, slot, 1, 1);
            CP_COMMIT();
        }
    }
    CP_WAIT(0);
}

// ---------------------------------------------------------------------------
extern "C" void kernel_launch(void* const* d_in, const int* in_sizes, int n_in,
                              void* d_out, int out_size) {
    const float* x  = (const float*)d_in[0];
    const float* t  = (const float*)d_in[1];
    const float* tw = (const float*)d_in[2];
    const float* tb = (const float*)d_in[3];
    const float* W0 = (const float*)d_in[4];
    const float* b0 = (const float*)d_in[5];
    const float* W1 = (const float*)d_in[6];
    const float* b1 = (const float*)d_in[7];
    const float* W2 = (const float*)d_in[8];
    const float* b2 = (const float*)d_in[9];
    float* out = (float*)d_out;

    cudaFuncSetAttribute(k_mma2, cudaFuncAttributeMaxDynamicSharedMemorySize, 229376);

    __half *h1, *h2, *w;
    cudaGetSymbolAddress((void**)&h1, g_h1);
    cudaGetSymbolAddress((void**)&h2, g_h2);
    cudaGetSymbolAddress((void**)&w,  g_W);

    k_prep<<<1792, 256>>>(W1, W2, W0, t, tw, tb, b0);
    k_layer0<<<BSZ * 4, 256>>>(x, W0);
    k_mma2<<<148, 512, 229376>>>(h1, w, b1, b2, h2, out);
}

// round 15
// speedup vs baseline: 1.2836x; 1.0164x over previous
#include <cuda_runtime.h>
#include <cuda_fp16.h>
#include <math.h>
#include <stdint.h>

#define BSZ 1024
#define SLOTS 74   // 148-CTA persistent grid, 74 slots per N-half

// ---------------------------------------------------------------------------
// Global scratch (static __device__ arrays, allocation-free)
// ---------------------------------------------------------------------------
__device__ float g_ctb[BSZ * 256];              // b0 + temb @ W0[6:134]
__device__ __half g_peWsh[256 * 256];           // roll-avg(pe) @ W0[2:6], fp16
__device__ __half g_h1[(size_t)BSZ * 256 * 256];
__device__ __half g_h2[(size_t)BSZ * 256 * 256];
__device__ __half g_W[2 * 256 * 256];           // W^T fp16, [l][n][k]
__device__ unsigned int g_bar;                  // monotonic global barrier ctr

// ---------------------------------------------------------------------------
// PTX helpers (sm_75/80-era: valid on the harness's sm_103 target)
// ---------------------------------------------------------------------------
__device__ __forceinline__ uint32_t s2u(const void* p) {
    uint32_t a;
    asm("{ .reg .u64 t; cvta.to.shared.u64 t, %1; cvt.u32.u64 %0, t; }"
        : "=r"(a) : "l"(p));
    return a;
}
#define CP_ASYNC16(dst, src) \
    asm volatile("cp.async.cg.shared.global [%0], [%1], 16;" :: "r"(dst), "l"(src))
#define CP_COMMIT() asm volatile("cp.async.commit_group;" ::: "memory")
#define CP_WAIT(n)  asm volatile("cp.async.wait_group %0;" :: "n"(n) : "memory")

__device__ __forceinline__ void ldsm4(uint32_t& r0, uint32_t& r1, uint32_t& r2,
                                      uint32_t& r3, uint32_t a) {
    asm volatile("ldmatrix.sync.aligned.m8n8.x4.shared.b16 {%0,%1,%2,%3}, [%4];"
                 : "=r"(r0), "=r"(r1), "=r"(r2), "=r"(r3) : "r"(a));
}
__device__ __forceinline__ void mma16816(float* d, const uint32_t* a,
                                         uint32_t b0, uint32_t b1) {
    asm volatile(
        "mma.sync.aligned.m16n8k16.row.col.f32.f16.f16.f32 "
        "{%0,%1,%2,%3}, {%4,%5,%6,%7}, {%8,%9}, {%0,%1,%2,%3};"
        : "+f"(d[0]), "+f"(d[1]), "+f"(d[2]), "+f"(d[3])
        : "r"(a[0]), "r"(a[1]), "r"(a[2]), "r"(a[3]), "r"(b0), "r"(b1));
}
// silu via single-MUFU tanh.approx: x*sigmoid(x) = 0.5x*tanh(0.5x) + 0.5x
__device__ __forceinline__ float fsilu(float x) {
    float t, h = 0.5f * x;
    asm("tanh.approx.f32 %0, %1;" : "=f"(t) : "f"(h));
    return fmaf(h, t, h);
}

// ---------------------------------------------------------------------------
// Kernel: merged prep.
//   blocks 0..511    : weights -> fp16 transposed [n][k]
//   blocks 512..767  : peWs[v][j] = roll-avg(pe) @ W0[2:6], fp16
//   blocks 768..1791 : per-batch time embedding -> g_ctb (ILP-optimized:
//                      4 independent accumulators, 2 threads per te output)
// ---------------------------------------------------------------------------
__global__ void __launch_bounds__(256) k_prep(
    const float* __restrict__ W1, const float* __restrict__ W2,
    const float* __restrict__ W0, const float* __restrict__ t,
    const float* __restrict__ tw, const float* __restrict__ tb,
    const float* __restrict__ b0) {
    int bb = blockIdx.x, tid = threadIdx.x;
    if (bb < 512) {
        int l = bb >> 8, k = bb & 255;
        const float* W = l ? W2 : W1;
        g_W[l * 65536 + tid * 256 + k] = __float2half(W[k * 256 + tid]);
        return;
    }
    if (bb < 768) {
        int v = bb - 512, j = tid;
        const float dth = 6.283185307179586f / 256.0f;
        float f1 = (1.0f + 2.0f * cosf(dth)) / 3.0f;
        float f2 = (1.0f + 2.0f * cosf(2.0f * dth)) / 3.0f;
        float th = dth * (float)v;
        float s1 = sinf(th), c1 = cosf(th);
        float s2 = sinf(2.0f * th), c2 = cosf(2.0f * th);
        g_peWsh[v * 256 + j] = __float2half(
            f1 * (s1 * W0[2 * 256 + j] + c1 * W0[3 * 256 + j]) +
            f2 * (s2 * W0[4 * 256 + j] + c2 * W0[5 * 256 + j]));
        return;
    }
    // time embedding (ILP: no serial 128-deep chains)
    int b = bb - 768;
    __shared__ float emb[128];
    __shared__ float tp[2][128];
    __shared__ float te[128];
    if (tid < 64) {
        float fr = expf(-9.210340371976184f * (float)tid / 63.0f);
        float a = t[b] * fr;
        emb[tid]      = sinf(a);
        emb[tid + 64] = cosf(a);
    }
    __syncthreads();
    {
        // te partials: 2 threads per output, 64 terms each, 4 accumulators
        int j = tid & 127, hf = tid >> 7;
        const float* twp = tw + (hf * 64) * 128 + j;
        const float* ep  = emb + hf * 64;
        float a0 = 0.f, a1 = 0.f, a2 = 0.f, a3 = 0.f;
#pragma unroll 8
        for (int i = 0; i < 64; i += 4) {
            a0 += ep[i]     * twp[i * 128];
            a1 += ep[i + 1] * twp[(i + 1) * 128];
            a2 += ep[i + 2] * twp[(i + 2) * 128];
            a3 += ep[i + 3] * twp[(i + 3) * 128];
        }
        tp[hf][j] = (a0 + a1) + (a2 + a3);
    }
    __syncthreads();
    if (tid < 128) {
        float acc = tb[tid] + tp[0][tid] + tp[1][tid];
        te[tid] = acc / (1.0f + expf(-acc));
    }
    __syncthreads();
    {
        // ctb: 256 outputs, 128 terms, 4 accumulators
        const float* wp = W0 + 6 * 256 + tid;
        float a0 = 0.f, a1 = 0.f, a2 = 0.f, a3 = 0.f;
#pragma unroll 8
        for (int k = 0; k < 128; k += 4) {
            a0 += te[k]     * wp[k * 256];
            a1 += te[k + 1] * wp[(k + 1) * 256];
            a2 += te[k + 2] * wp[(k + 2) * 256];
            a3 += te[k + 3] * wp[(k + 3) * 256];
        }
        g_ctb[b * 256 + tid] = b0[tid] + (a0 + a1) + (a2 + a3);
    }
}

// ---------------------------------------------------------------------------
// Kernel: layer 0 collapsed, fp32 math + f32 tanh (validated config),
// peW rows prefetched to smem via cp.async.
// grid = 4096 (b, v-quarter), block = 256 (128 col-pairs x 2 v-groups of 32).
// ---------------------------------------------------------------------------
__global__ void __launch_bounds__(256) k_layer0(const float* __restrict__ x,
                                                const float* __restrict__ W0) {
    __shared__ float xs[512];
    __shared__ float xa[256], ya[256];
    __shared__ __half pws[66 * 256];   // rows v0-1 .. v0+64 of peWsh (33 KB)
    int b = blockIdx.x >> 2, vq = blockIdx.x & 3;
    int tid = threadIdx.x;
    int v0q = vq * 64;

    // prefetch peW rows (wrap-around source rows -> linear smem rows)
    {
        uint32_t pb = s2u(pws);
        const char* src = (const char*)g_peWsh;
        int base = (v0q + 255) & 255;
#pragma unroll
        for (int i = tid; i < 66 * 32; i += 256) {
            int row = i >> 5, seg = i & 31;
            int vsrc = (base + row) & 255;
            CP_ASYNC16(pb + row * 512 + seg * 16, src + vsrc * 512 + seg * 16);
        }
        CP_COMMIT();
    }

    for (int i = tid; i < 512; i += 256) xs[i] = x[b * 512 + i];
    __syncthreads();
    {
        int v = tid, vm = (v + 255) & 255, vp = (v + 1) & 255;
        xa[v] = (xs[2 * vm] + xs[2 * v] + xs[2 * vp]) * (1.0f / 3.0f);
        ya[v] = (xs[2 * vm + 1] + xs[2 * v + 1] + xs[2 * vp + 1]) * (1.0f / 3.0f);
    }
    CP_WAIT(0);
    __syncthreads();

    int cp = tid & 127, vg = tid >> 7, c0 = 2 * cp;
    float w00 = W0[c0], w01 = W0[c0 + 1];
    float w10 = W0[256 + c0], w11 = W0[256 + c0 + 1];
    float cb0 = g_ctb[b * 256 + c0], cb1 = g_ctb[b * 256 + c0 + 1];
    int j0 = vg * 32 + 1;   // local row of first output v

#define HEVAL(JJ, H0, H1)                                                  \
    do {                                                                   \
        int _j = (JJ);                                                     \
        float2 pw = __half22float2(*(const __half2*)(pws + _j * 256 + c0));\
        int _v = (v0q + _j - 1) & 255;                                     \
        float _xv = xa[_v], _yv = ya[_v];                                  \
        float a0 = fmaf(_xv, w00, fmaf(_yv, w10, pw.x + cb0));             \
        float a1 = fmaf(_xv, w01, fmaf(_yv, w11, pw.y + cb1));             \
        H0 = fsilu(a0); H1 = fsilu(a1);                                    \
    } while (0)

    float hm0, hm1, hc0, hc1;
    HEVAL(j0 - 1, hm0, hm1);
    HEVAL(j0, hc0, hc1);
    __half* Og = g_h1 + (size_t)b * 65536 + (size_t)(v0q + vg * 32) * 256 + c0;
#pragma unroll 8
    for (int j = j0; j < j0 + 32; j++) {
        float hp0, hp1;
        HEVAL(j + 1, hp0, hp1);
        float t0 = (hm0 + hc0 + hp0) * (1.0f / 3.0f);
        float t1 = (hm1 + hc1 + hp1) * (1.0f / 3.0f);
        *(__half2*)Og = __floats2half2_rn(t0, t1);
        Og += 256;
        hm0 = hc0; hm1 = hc1; hc0 = hp0; hc1 = hp1;
    }
#undef HEVAL
}

// ---------------------------------------------------------------------------
// MERGED persistent fp16 mma.sync kernel: layer1 + global barrier + layer2.
// grid = 148 (1 CTA/SM, all resident -> barrier-safe), block = 512.
// CTA pinned to nh; loops over b = slot + i*74, twice (lay 0 then lay 1).
// B resident per layer (W2 prefetched into the B region BEFORE the barrier,
// overlapping the barrier wait). A streamed via 3-buffer cp.async ring.
// Barrier: monotonic counter, phase = old/148 (graph-replay-safe, no reset).
// ---------------------------------------------------------------------------
__global__ void __launch_bounds__(512, 1) k_mma2(
    const __half* __restrict__ A1, const __half* __restrict__ W,
    const float* __restrict__ b1, const float* __restrict__ b2,
    __half* __restrict__ H2, float* __restrict__ out) {
    extern __shared__ __align__(1024) char smc[];
    const uint32_t smb = s2u(smc);
    const int tid = threadIdx.x, wid = tid >> 5, lane = tid & 31;
    const int nh = blockIdx.x & 1, slot = blockIdx.x >> 1;
    const int wm = wid >> 2, wn = wid & 3;

    const uint32_t OFF_B = 98304u, OFF_S = 163840u;

    const int nt = (1024 - slot + 73) / 74;

    const int ar = tid >> 3, ac = tid & 7;
    const uint32_t swcA = (uint32_t)((ac * 16) ^ ((ar & 7) << 4));

#define ISSUE_A(AGL, BIDX, CH, BUF)                                          \
    do {                                                                     \
        const __half* _Ag = (AGL) + (size_t)(BIDX) * 65536;                  \
        uint32_t _dst = smb + (uint32_t)(BUF) * 32768u;                      \
        _Pragma("unroll") for (int _j = 0; _j < 4; _j++) {                   \
            int _row = ar + _j * 64;                                         \
            CP_ASYNC16(_dst + _row * 128 + swcA,                             \
                       _Ag + _row * 256 + (CH) * 64 + ac * 8);               \
        }                                                                    \
    } while (0)

#define ISSUE_B(BGL)                                                         \
    do {                                                                     \
        _Pragma("unroll") for (int _j = 0; _j < 8; _j++) {                   \
            int _idx = tid + _j * 512;                                       \
            int _cS = _idx >> 10, _row = (_idx >> 3) & 127, _ab = _idx & 7;  \
            uint32_t _swc = (uint32_t)((_ab * 16) ^ ((_row & 7) << 4));      \
            CP_ASYNC16(smb + OFF_B + _cS * 16384 + _row * 128 + _swc,        \
                       (BGL) + _row * 256 + _cS * 64 + _ab * 8);             \
        }                                                                    \
    } while (0)

    const int li = lane >> 3, lr = lane & 7;
    uint32_t colk[4];
#pragma unroll
    for (int kt = 0; kt < 4; kt++)
        colk[kt] = (uint32_t)((kt * 32 + (li >> 1) * 16) ^ (lr << 4));
    const uint32_t aRow = smb + (uint32_t)(wm * 64 + (li & 1) * 8 + lr) * 128;
    const uint32_t bRow = smb + OFF_B + (uint32_t)(wn * 32 + (li & 1) * 8 + lr) * 128;
    const int r = lane >> 2, l2 = (lane & 3) * 2;

    // layer-0 prologue: B1 + A chunk 0 (group 0), A chunk 1 (group 1)
    ISSUE_B(W + nh * 32768);
    ISSUE_A(A1, slot, 0, 0);
    CP_COMMIT();
    ISSUE_A(A1, slot, 1, 1);
    CP_COMMIT();

    for (int lay = 0; lay < 2; lay++) {
        const __half* Agl = lay ? (const __half*)H2 : A1;
        const float* bias = lay ? b2 : b1;
        const int NC = 4 * nt;

        float bj[4][2];
#pragma unroll
        for (int nt2 = 0; nt2 < 4; nt2++) {
            int n = nh * 128 + wn * 32 + nt2 * 8 + l2;
            bj[nt2][0] = bias[n];
            bj[nt2][1] = bias[n + 1];
        }

        int g = 0;
        for (int i = 0; i < nt; i++) {
            const int b = slot + i * SLOTS;

            float acc[4][4][4];
#pragma unroll
            for (int mt = 0; mt < 4; mt++)
#pragma unroll
                for (int nt2 = 0; nt2 < 4; nt2++)
#pragma unroll
                    for (int q = 0; q < 4; q++) acc[mt][nt2][q] = 0.0f;

            for (int c = 0; c < 4; c++) {
                CP_WAIT(1);
                __syncthreads();
                int gn = g + 2;
                if (gn < NC) ISSUE_A(Agl, slot + (gn >> 2) * SLOTS, gn & 3, gn % 3);
                CP_COMMIT();

                const uint32_t aB = aRow + (uint32_t)(g % 3) * 32768u;
                const uint32_t bB = bRow + (uint32_t)c * 16384u;
#pragma unroll
                for (int kt = 0; kt < 4; kt++) {
                    uint32_t ah[4][4];
#pragma unroll
                    for (int mt = 0; mt < 4; mt++)
                        ldsm4(ah[mt][0], ah[mt][1], ah[mt][2], ah[mt][3],
                              aB + mt * 2048 + colk[kt]);
#pragma unroll
                    for (int p = 0; p < 2; p++) {
                        uint32_t bh[4];
                        ldsm4(bh[0], bh[1], bh[2], bh[3], bB + p * 2048 + colk[kt]);
#pragma unroll
                        for (int mt = 0; mt < 4; mt++)
#pragma unroll
                            for (int s = 0; s < 2; s++)
                                mma16816(acc[mt][p * 2 + s], ah[mt], bh[s], bh[2 + s]);
                    }
                }
                g++;
            }

            if (lay == 0) {
                // intermediate epilogue: silu -> swizzled half2 stage -> roll -> H2
#pragma unroll
                for (int mt = 0; mt < 4; mt++)
#pragma unroll
                    for (int nt2 = 0; nt2 < 4; nt2++) {
                        int v = wm * 64 + mt * 16 + r;
                        uint32_t scol =
                            (uint32_t)(((wn * 32 + nt2 * 8 + l2) * 2) ^ (r << 4));
                        *(__half2*)(smc + OFF_S + v * 256 + scol) = __floats2half2_rn(
                            fsilu(acc[mt][nt2][0] + bj[nt2][0]),
                            fsilu(acc[mt][nt2][1] + bj[nt2][1]));
                        *(__half2*)(smc + OFF_S + (v + 8) * 256 + scol) =
                            __floats2half2_rn(
                                fsilu(acc[mt][nt2][2] + bj[nt2][0]),
                                fsilu(acc[mt][nt2][3] + bj[nt2][1]));
                    }
                __syncthreads();
                int np = tid & 31, vgE = tid >> 5;
                __half* Og = H2 + (size_t)b * 65536 + nh * 128 + 4 * np;
                const __half2 third = __floats2half2_rn(1.0f / 3.0f, 1.0f / 3.0f);
#pragma unroll 4
                for (int v = vgE * 16; v < vgE * 16 + 16; v++) {
                    int vm = (v + 255) & 255, vp = (v + 1) & 255;
                    uint2 ua = *(const uint2*)(smc + OFF_S + vm * 256 +
                                               ((8 * np) ^ ((vm & 7) << 4)));
                    uint2 ub = *(const uint2*)(smc + OFF_S + v * 256 +
                                               ((8 * np) ^ ((v & 7) << 4)));
                    uint2 uc = *(const uint2*)(smc + OFF_S + vp * 256 +
                                               ((8 * np) ^ ((vp & 7) << 4)));
                    __half2 r0 = __hmul2(__hadd2(__hadd2(*(__half2*)&ua.x,
                                                         *(__half2*)&ub.x),
                                                 *(__half2*)&uc.x), third);
                    __half2 r1 = __hmul2(__hadd2(__hadd2(*(__half2*)&ua.y,
                                                         *(__half2*)&ub.y),
                                                 *(__half2*)&uc.y), third);
                    uint2 res;
                    res.x = *(uint32_t*)&r0;
                    res.y = *(uint32_t*)&r1;
                    *(uint2*)(Og + (size_t)v * 256) = res;
                }
                __syncthreads();
            } else {
                // final epilogue: silu in regs + mean pool, shfl + smem reduce
                float cs[4][2];
#pragma unroll
                for (int nt2 = 0; nt2 < 4; nt2++) { cs[nt2][0] = 0.0f; cs[nt2][1] = 0.0f; }
#pragma unroll
                for (int mt = 0; mt < 4; mt++)
#pragma unroll
                    for (int nt2 = 0; nt2 < 4; nt2++) {
                        cs[nt2][0] += fsilu(acc[mt][nt2][0] + bj[nt2][0]) +
                                      fsilu(acc[mt][nt2][2] + bj[nt2][0]);
                        cs[nt2][1] += fsilu(acc[mt][nt2][1] + bj[nt2][1]) +
                                      fsilu(acc[mt][nt2][3] + bj[nt2][1]);
                    }
#pragma unroll
                for (int off = 4; off <= 16; off <<= 1)
#pragma unroll
                    for (int nt2 = 0; nt2 < 4; nt2++) {
                        cs[nt2][0] += __shfl_xor_sync(0xFFFFFFFFu, cs[nt2][0], off);
                        cs[nt2][1] += __shfl_xor_sync(0xFFFFFFFFu, cs[nt2][1], off);
                    }
                float* red = (float*)(smc + OFF_S);
                if (r == 0) {
#pragma unroll
                    for (int nt2 = 0; nt2 < 4; nt2++) {
                        int n = wn * 32 + nt2 * 8 + l2;
                        red[wm * 128 + n]     = cs[nt2][0];
                        red[wm * 128 + n + 1] = cs[nt2][1];
                    }
                }
                __syncthreads();
                if (tid < 128)
                    out[b * 256 + nh * 128 + tid] =
                        (red[tid] + red[128 + tid] + red[256 + tid] + red[384 + tid]) *
                        (1.0f / 256.0f);
                __syncthreads();
            }
        }

        if (lay == 0) {
            CP_WAIT(0);          // drain layer-1 A pipeline
            __syncthreads();
            ISSUE_B(W + 65536 + nh * 32768);   // prefetch W2 (overlaps barrier)
            CP_COMMIT();
            __threadfence();     // release H2 stores
            __syncthreads();
            if (tid == 0) {
                unsigned int old = atomicAdd(&g_bar, 1u);
                unsigned int target = (old / 148u + 1u) * 148u;
                unsigned int cur;
                do {
                    asm volatile("ld.acquire.gpu.u32 %0, [%1];"
                                 : "=r"(cur) : "l"(&g_bar));
                    if (cur < target) __nanosleep(256);
                } while (cur < target);
            }
            __syncthreads();
            // prime layer-2 A pipeline (B2 already in flight as earlier group)
            ISSUE_A(H2, slot, 0, 0);
            CP_COMMIT();
            ISSUE_A(H2, slot, 1, 1);
            CP_COMMIT();
        }
    }
    CP_WAIT(0);
}

// ---------------------------------------------------------------------------
extern "C" void kernel_launch(void* const* d_in, const int* in_sizes, int n_in,
                              void* d_out, int out_size) {
    const float* x  = (const float*)d_in[0];
    const float* t  = (const float*)d_in[1];
    const float* tw = (const float*)d_in[2];
    const float* tb = (const float*)d_in[3];
    const float* W0 = (const float*)d_in[4];
    const float* b0 = (const float*)d_in[5];
    const float* W1 = (const float*)d_in[6];
    const float* b1 = (const float*)d_in[7];
    const float* W2 = (const float*)d_in[8];
    const float* b2 = (const float*)d_in[9];
    float* out = (float*)d_out;

    cudaFuncSetAttribute(k_mma2, cudaFuncAttributeMaxDynamicSharedMemorySize, 229376);

    __half *h1, *h2, *w;
    cudaGetSymbolAddress((void**)&h1, g_h1);
    cudaGetSymbolAddress((void**)&h2, g_h2);
    cudaGetSymbolAddress((void**)&w,  g_W);

    k_prep<<<1792, 256>>>(W1, W2, W0, t, tw, tb, b0);
    k_layer0<<<BSZ * 4, 256>>>(x, W0);
    k_mma2<<<148, 512, 229376>>>(h1, w, b1, b2, h2, out);
}

// round 16
// speedup vs baseline: 1.2864x; 1.0022x over previous
#include <cuda_runtime.h>
#include <cuda_fp16.h>
#include <math.h>
#include <stdint.h>

#define BSZ 1024
#define SLOTS 74   // 148-CTA persistent grid, 74 slots per N-half

// ---------------------------------------------------------------------------
// Global scratch (static __device__ arrays, allocation-free)
// ---------------------------------------------------------------------------
__device__ float g_ctb[BSZ * 256];              // b0 + temb @ W0[6:134]
__device__ __half g_peWsh[256 * 256];           // roll-avg(pe) @ W0[2:6], fp16
__device__ __half g_h1[(size_t)BSZ * 256 * 256];
__device__ __half g_h2[(size_t)BSZ * 256 * 256];
__device__ __half g_W[2 * 256 * 256];           // W^T fp16, [l][n][k]
__device__ unsigned int g_bar;                  // monotonic global barrier ctr

// ---------------------------------------------------------------------------
// PTX helpers (sm_75/80-era: valid on the harness's sm_103 target)
// ---------------------------------------------------------------------------
__device__ __forceinline__ uint32_t s2u(const void* p) {
    uint32_t a;
    asm("{ .reg .u64 t; cvta.to.shared.u64 t, %1; cvt.u32.u64 %0, t; }"
        : "=r"(a) : "l"(p));
    return a;
}
#define CP_ASYNC16(dst, src) \
    asm volatile("cp.async.cg.shared.global [%0], [%1], 16;" :: "r"(dst), "l"(src))
#define CP_COMMIT() asm volatile("cp.async.commit_group;" ::: "memory")
#define CP_WAIT(n)  asm volatile("cp.async.wait_group %0;" :: "n"(n) : "memory")

__device__ __forceinline__ void ldsm4(uint32_t& r0, uint32_t& r1, uint32_t& r2,
                                      uint32_t& r3, uint32_t a) {
    asm volatile("ldmatrix.sync.aligned.m8n8.x4.shared.b16 {%0,%1,%2,%3}, [%4];"
                 : "=r"(r0), "=r"(r1), "=r"(r2), "=r"(r3) : "r"(a));
}
__device__ __forceinline__ void mma16816(float* d, const uint32_t* a,
                                         uint32_t b0, uint32_t b1) {
    asm volatile(
        "mma.sync.aligned.m16n8k16.row.col.f32.f16.f16.f32 "
        "{%0,%1,%2,%3}, {%4,%5,%6,%7}, {%8,%9}, {%0,%1,%2,%3};"
        : "+f"(d[0]), "+f"(d[1]), "+f"(d[2]), "+f"(d[3])
        : "r"(a[0]), "r"(a[1]), "r"(a[2]), "r"(a[3]), "r"(b0), "r"(b1));
}
// silu via single-MUFU tanh.approx: x*sigmoid(x) = 0.5x*tanh(0.5x) + 0.5x
__device__ __forceinline__ float fsilu(float x) {
    float t, h = 0.5f * x;
    asm("tanh.approx.f32 %0, %1;" : "=f"(t) : "f"(h));
    return fmaf(h, t, h);
}

// ---------------------------------------------------------------------------
// Kernel: merged prep.
//   blocks 0..127    : weights -> fp16 transposed [n][k], smem-tiled
//                      (coalesced reads AND writes; 32x33 tile, 4 elem/thr)
//   blocks 128..383  : peWs[v][j] = roll-avg(pe) @ W0[2:6], fp16 (__sinf)
//   blocks 384..1407 : per-batch time embedding -> g_ctb (ILP: 4 accums)
// ---------------------------------------------------------------------------
__global__ void __launch_bounds__(256) k_prep(
    const float* __restrict__ W1, const float* __restrict__ W2,
    const float* __restrict__ W0, const float* __restrict__ t,
    const float* __restrict__ tw, const float* __restrict__ tb,
    const float* __restrict__ b0) {
    int bb = blockIdx.x, tid = threadIdx.x;
    if (bb < 128) {
        // smem-tiled transpose: W[k][n] -> g_W[l][n][k] (fp16)
        __shared__ float ts[32][33];
        int l = bb >> 6, tile = bb & 63;
        int kt = tile >> 3, nt = tile & 7;
        int tc = tid & 31, tr = tid >> 5;   // 8 rows per pass
        const float* W = l ? W2 : W1;
#pragma unroll
        for (int q = 0; q < 4; q++) {
            int r = tr + q * 8;
            ts[r][tc] = W[(kt * 32 + r) * 256 + nt * 32 + tc];   // coalesced
        }
        __syncthreads();
#pragma unroll
        for (int q = 0; q < 4; q++) {
            int r = tr + q * 8;                                   // n within tile
            g_W[l * 65536 + (nt * 32 + r) * 256 + kt * 32 + tc] =
                __float2half(ts[tc][r]);                          // coalesced
        }
        return;
    }
    if (bb < 384) {
        int v = bb - 128, j = tid;
        const float dth = 6.283185307179586f / 256.0f;
        float f1 = (1.0f + 2.0f * __cosf(dth)) / 3.0f;
        float f2 = (1.0f + 2.0f * __cosf(2.0f * dth)) / 3.0f;
        float th = dth * (float)v;
        float s1 = __sinf(th), c1 = __cosf(th);
        float s2 = __sinf(2.0f * th), c2 = __cosf(2.0f * th);
        g_peWsh[v * 256 + j] = __float2half(
            f1 * (s1 * W0[2 * 256 + j] + c1 * W0[3 * 256 + j]) +
            f2 * (s2 * W0[4 * 256 + j] + c2 * W0[5 * 256 + j]));
        return;
    }
    // time embedding (ILP: no serial 128-deep chains)
    int b = bb - 384;
    __shared__ float emb[128];
    __shared__ float tp[2][128];
    __shared__ float te[128];
    if (tid < 64) {
        float fr = expf(-9.210340371976184f * (float)tid / 63.0f);
        float a = t[b] * fr;
        emb[tid]      = sinf(a);
        emb[tid + 64] = cosf(a);
    }
    __syncthreads();
    {
        // te partials: 2 threads per output, 64 terms each, 4 accumulators
        int j = tid & 127, hf = tid >> 7;
        const float* twp = tw + (hf * 64) * 128 + j;
        const float* ep  = emb + hf * 64;
        float a0 = 0.f, a1 = 0.f, a2 = 0.f, a3 = 0.f;
#pragma unroll 8
        for (int i = 0; i < 64; i += 4) {
            a0 += ep[i]     * twp[i * 128];
            a1 += ep[i + 1] * twp[(i + 1) * 128];
            a2 += ep[i + 2] * twp[(i + 2) * 128];
            a3 += ep[i + 3] * twp[(i + 3) * 128];
        }
        tp[hf][j] = (a0 + a1) + (a2 + a3);
    }
    __syncthreads();
    if (tid < 128) {
        float acc = tb[tid] + tp[0][tid] + tp[1][tid];
        te[tid] = acc / (1.0f + expf(-acc));
    }
    __syncthreads();
    {
        // ctb: 256 outputs, 128 terms, 4 accumulators
        const float* wp = W0 + 6 * 256 + tid;
        float a0 = 0.f, a1 = 0.f, a2 = 0.f, a3 = 0.f;
#pragma unroll 8
        for (int k = 0; k < 128; k += 4) {
            a0 += te[k]     * wp[k * 256];
            a1 += te[k + 1] * wp[(k + 1) * 256];
            a2 += te[k + 2] * wp[(k + 2) * 256];
            a3 += te[k + 3] * wp[(k + 3) * 256];
        }
        g_ctb[b * 256 + tid] = b0[tid] + (a0 + a1) + (a2 + a3);
    }
}

// ---------------------------------------------------------------------------
// Kernel: layer 0 collapsed, fp32 math + f32 tanh (validated config),
// peW rows prefetched to smem via cp.async.
// grid = 4096 (b, v-quarter), block = 256 (128 col-pairs x 2 v-groups of 32).
// ---------------------------------------------------------------------------
__global__ void __launch_bounds__(256) k_layer0(const float* __restrict__ x,
                                                const float* __restrict__ W0) {
    __shared__ float xs[512];
    __shared__ float xa[256], ya[256];
    __shared__ __half pws[66 * 256];   // rows v0-1 .. v0+64 of peWsh (33 KB)
    int b = blockIdx.x >> 2, vq = blockIdx.x & 3;
    int tid = threadIdx.x;
    int v0q = vq * 64;

    // prefetch peW rows (wrap-around source rows -> linear smem rows)
    {
        uint32_t pb = s2u(pws);
        const char* src = (const char*)g_peWsh;
        int base = (v0q + 255) & 255;
#pragma unroll
        for (int i = tid; i < 66 * 32; i += 256) {
            int row = i >> 5, seg = i & 31;
            int vsrc = (base + row) & 255;
            CP_ASYNC16(pb + row * 512 + seg * 16, src + vsrc * 512 + seg * 16);
        }
        CP_COMMIT();
    }

    for (int i = tid; i < 512; i += 256) xs[i] = x[b * 512 + i];
    __syncthreads();
    {
        int v = tid, vm = (v + 255) & 255, vp = (v + 1) & 255;
        xa[v] = (xs[2 * vm] + xs[2 * v] + xs[2 * vp]) * (1.0f / 3.0f);
        ya[v] = (xs[2 * vm + 1] + xs[2 * v + 1] + xs[2 * vp + 1]) * (1.0f / 3.0f);
    }
    CP_WAIT(0);
    __syncthreads();

    int cp = tid & 127, vg = tid >> 7, c0 = 2 * cp;
    float w00 = W0[c0], w01 = W0[c0 + 1];
    float w10 = W0[256 + c0], w11 = W0[256 + c0 + 1];
    float cb0 = g_ctb[b * 256 + c0], cb1 = g_ctb[b * 256 + c0 + 1];
    int j0 = vg * 32 + 1;   // local row of first output v

#define HEVAL(JJ, H0, H1)                                                  \
    do {                                                                   \
        int _j = (JJ);                                                     \
        float2 pw = __half22float2(*(const __half2*)(pws + _j * 256 + c0));\
        int _v = (v0q + _j - 1) & 255;                                     \
        float _xv = xa[_v], _yv = ya[_v];                                  \
        float a0 = fmaf(_xv, w00, fmaf(_yv, w10, pw.x + cb0));             \
        float a1 = fmaf(_xv, w01, fmaf(_yv, w11, pw.y + cb1));             \
        H0 = fsilu(a0); H1 = fsilu(a1);                                    \
    } while (0)

    float hm0, hm1, hc0, hc1;
    HEVAL(j0 - 1, hm0, hm1);
    HEVAL(j0, hc0, hc1);
    __half* Og = g_h1 + (size_t)b * 65536 + (size_t)(v0q + vg * 32) * 256 + c0;
#pragma unroll 8
    for (int j = j0; j < j0 + 32; j++) {
        float hp0, hp1;
        HEVAL(j + 1, hp0, hp1);
        float t0 = (hm0 + hc0 + hp0) * (1.0f / 3.0f);
        float t1 = (hm1 + hc1 + hp1) * (1.0f / 3.0f);
        *(__half2*)Og = __floats2half2_rn(t0, t1);
        Og += 256;
        hm0 = hc0; hm1 = hc1; hc0 = hp0; hc1 = hp1;
    }
#undef HEVAL
}

// ---------------------------------------------------------------------------
// MERGED persistent fp16 mma.sync kernel: layer1 + global barrier + layer2.
// grid = 148 (1 CTA/SM, all resident -> barrier-safe), block = 512.
// CTA pinned to nh; loops over b = slot + i*74, twice (lay 0 then lay 1).
// B resident per layer (W2 prefetched into the B region BEFORE the barrier,
// overlapping the barrier wait). A streamed via 3-buffer cp.async ring.
// Barrier: monotonic counter, phase = old/148 (graph-replay-safe, no reset).
// ---------------------------------------------------------------------------
__global__ void __launch_bounds__(512, 1) k_mma2(
    const __half* __restrict__ A1, const __half* __restrict__ W,
    const float* __restrict__ b1, const float* __restrict__ b2,
    __half* __restrict__ H2, float* __restrict__ out) {
    extern __shared__ __align__(1024) char smc[];
    const uint32_t smb = s2u(smc);
    const int tid = threadIdx.x, wid = tid >> 5, lane = tid & 31;
    const int nh = blockIdx.x & 1, slot = blockIdx.x >> 1;
    const int wm = wid >> 2, wn = wid & 3;

    const uint32_t OFF_B = 98304u, OFF_S = 163840u;

    const int nt = (1024 - slot + 73) / 74;

    const int ar = tid >> 3, ac = tid & 7;
    const uint32_t swcA = (uint32_t)((ac * 16) ^ ((ar & 7) << 4));

#define ISSUE_A(AGL, BIDX, CH, BUF)                                          \
    do {                                                                     \
        const __half* _Ag = (AGL) + (size_t)(BIDX) * 65536;                  \
        uint32_t _dst = smb + (uint32_t)(BUF) * 32768u;                      \
        _Pragma("unroll") for (int _j = 0; _j < 4; _j++) {                   \
            int _row = ar + _j * 64;                                         \
            CP_ASYNC16(_dst + _row * 128 + swcA,                             \
                       _Ag + _row * 256 + (CH) * 64 + ac * 8);               \
        }                                                                    \
    } while (0)

#define ISSUE_B(BGL)                                                         \
    do {                                                                     \
        _Pragma("unroll") for (int _j = 0; _j < 8; _j++) {                   \
            int _idx = tid + _j * 512;                                       \
            int _cS = _idx >> 10, _row = (_idx >> 3) & 127, _ab = _idx & 7;  \
            uint32_t _swc = (uint32_t)((_ab * 16) ^ ((_row & 7) << 4));      \
            CP_ASYNC16(smb + OFF_B + _cS * 16384 + _row * 128 + _swc,        \
                       (BGL) + _row * 256 + _cS * 64 + _ab * 8);             \
        }                                                                    \
    } while (0)

    const int li = lane >> 3, lr = lane & 7;
    uint32_t colk[4];
#pragma unroll
    for (int kt = 0; kt < 4; kt++)
        colk[kt] = (uint32_t)((kt * 32 + (li >> 1) * 16) ^ (lr << 4));
    const uint32_t aRow = smb + (uint32_t)(wm * 64 + (li & 1) * 8 + lr) * 128;
    const uint32_t bRow = smb + OFF_B + (uint32_t)(wn * 32 + (li & 1) * 8 + lr) * 128;
    const int r = lane >> 2, l2 = (lane & 3) * 2;

    // layer-0 prologue: B1 + A chunk 0 (group 0), A chunk 1 (group 1)
    ISSUE_B(W + nh * 32768);
    ISSUE_A(A1, slot, 0, 0);
    CP_COMMIT();
    ISSUE_A(A1, slot, 1, 1);
    CP_COMMIT();

    for (int lay = 0; lay < 2; lay++) {
        const __half* Agl = lay ? (const __half*)H2 : A1;
        const float* bias = lay ? b2 : b1;
        const int NC = 4 * nt;

        float bj[4][2];
#pragma unroll
        for (int nt2 = 0; nt2 < 4; nt2++) {
            int n = nh * 128 + wn * 32 + nt2 * 8 + l2;
            bj[nt2][0] = bias[n];
            bj[nt2][1] = bias[n + 1];
        }

        int g = 0;
        for (int i = 0; i < nt; i++) {
            const int b = slot + i * SLOTS;

            float acc[4][4][4];
#pragma unroll
            for (int mt = 0; mt < 4; mt++)
#pragma unroll
                for (int nt2 = 0; nt2 < 4; nt2++)
#pragma unroll
                    for (int q = 0; q < 4; q++) acc[mt][nt2][q] = 0.0f;

            for (int c = 0; c < 4; c++) {
                CP_WAIT(1);
                __syncthreads();
                int gn = g + 2;
                if (gn < NC) ISSUE_A(Agl, slot + (gn >> 2) * SLOTS, gn & 3, gn % 3);
                CP_COMMIT();

                const uint32_t aB = aRow + (uint32_t)(g % 3) * 32768u;
                const uint32_t bB = bRow + (uint32_t)c * 16384u;
#pragma unroll
                for (int kt = 0; kt < 4; kt++) {
                    uint32_t ah[4][4];
#pragma unroll
                    for (int mt = 0; mt < 4; mt++)
                        ldsm4(ah[mt][0], ah[mt][1], ah[mt][2], ah[mt][3],
                              aB + mt * 2048 + colk[kt]);
#pragma unroll
                    for (int p = 0; p < 2; p++) {
                        uint32_t bh[4];
                        ldsm4(bh[0], bh[1], bh[2], bh[3], bB + p * 2048 + colk[kt]);
#pragma unroll
                        for (int mt = 0; mt < 4; mt++)
#pragma unroll
                            for (int s = 0; s < 2; s++)
                                mma16816(acc[mt][p * 2 + s], ah[mt], bh[s], bh[2 + s]);
                    }
                }
                g++;
            }

            if (lay == 0) {
                // intermediate epilogue: silu -> swizzled half2 stage -> roll -> H2
#pragma unroll
                for (int mt = 0; mt < 4; mt++)
#pragma unroll
                    for (int nt2 = 0; nt2 < 4; nt2++) {
                        int v = wm * 64 + mt * 16 + r;
                        uint32_t scol =
                            (uint32_t)(((wn * 32 + nt2 * 8 + l2) * 2) ^ (r << 4));
                        *(__half2*)(smc + OFF_S + v * 256 + scol) = __floats2half2_rn(
                            fsilu(acc[mt][nt2][0] + bj[nt2][0]),
                            fsilu(acc[mt][nt2][1] + bj[nt2][1]));
                        *(__half2*)(smc + OFF_S + (v + 8) * 256 + scol) =
                            __floats2half2_rn(
                                fsilu(acc[mt][nt2][2] + bj[nt2][0]),
                                fsilu(acc[mt][nt2][3] + bj[nt2][1]));
                    }
                __syncthreads();
                int np = tid & 31, vgE = tid >> 5;
                __half* Og = H2 + (size_t)b * 65536 + nh * 128 + 4 * np;
                const __half2 third = __floats2half2_rn(1.0f / 3.0f, 1.0f / 3.0f);
#pragma unroll 4
                for (int v = vgE * 16; v < vgE * 16 + 16; v++) {
                    int vm = (v + 255) & 255, vp = (v + 1) & 255;
                    uint2 ua = *(const uint2*)(smc + OFF_S + vm * 256 +
                                               ((8 * np) ^ ((vm & 7) << 4)));
                    uint2 ub = *(const uint2*)(smc + OFF_S + v * 256 +
                                               ((8 * np) ^ ((v & 7) << 4)));
                    uint2 uc = *(const uint2*)(smc + OFF_S + vp * 256 +
                                               ((8 * np) ^ ((vp & 7) << 4)));
                    __half2 r0 = __hmul2(__hadd2(__hadd2(*(__half2*)&ua.x,
                                                         *(__half2*)&ub.x),
                                                 *(__half2*)&uc.x), third);
                    __half2 r1 = __hmul2(__hadd2(__hadd2(*(__half2*)&ua.y,
                                                         *(__half2*)&ub.y),
                                                 *(__half2*)&uc.y), third);
                    uint2 res;
                    res.x = *(uint32_t*)&r0;
                    res.y = *(uint32_t*)&r1;
                    *(uint2*)(Og + (size_t)v * 256) = res;
                }
                __syncthreads();
            } else {
                // final epilogue: silu in regs + mean pool, shfl + smem reduce
                float cs[4][2];
#pragma unroll
                for (int nt2 = 0; nt2 < 4; nt2++) { cs[nt2][0] = 0.0f; cs[nt2][1] = 0.0f; }
#pragma unroll
                for (int mt = 0; mt < 4; mt++)
#pragma unroll
                    for (int nt2 = 0; nt2 < 4; nt2++) {
                        cs[nt2][0] += fsilu(acc[mt][nt2][0] + bj[nt2][0]) +
                                      fsilu(acc[mt][nt2][2] + bj[nt2][0]);
                        cs[nt2][1] += fsilu(acc[mt][nt2][1] + bj[nt2][1]) +
                                      fsilu(acc[mt][nt2][3] + bj[nt2][1]);
                    }
#pragma unroll
                for (int off = 4; off <= 16; off <<= 1)
#pragma unroll
                    for (int nt2 = 0; nt2 < 4; nt2++) {
                        cs[nt2][0] += __shfl_xor_sync(0xFFFFFFFFu, cs[nt2][0], off);
                        cs[nt2][1] += __shfl_xor_sync(0xFFFFFFFFu, cs[nt2][1], off);
                    }
                float* red = (float*)(smc + OFF_S);
                if (r == 0) {
#pragma unroll
                    for (int nt2 = 0; nt2 < 4; nt2++) {
                        int n = wn * 32 + nt2 * 8 + l2;
                        red[wm * 128 + n]     = cs[nt2][0];
                        red[wm * 128 + n + 1] = cs[nt2][1];
                    }
                }
                __syncthreads();
                if (tid < 128)
                    out[b * 256 + nh * 128 + tid] =
                        (red[tid] + red[128 + tid] + red[256 + tid] + red[384 + tid]) *
                        (1.0f / 256.0f);
                __syncthreads();
            }
        }

        if (lay == 0) {
            CP_WAIT(0);          // drain layer-1 A pipeline
            __syncthreads();
            ISSUE_B(W + 65536 + nh * 32768);   // prefetch W2 (overlaps barrier)
            CP_COMMIT();
            __threadfence();     // release H2 stores
            __syncthreads();
            if (tid == 0) {
                unsigned int old = atomicAdd(&g_bar, 1u);
                unsigned int target = (old / 148u + 1u) * 148u;
                unsigned int cur;
                do {
                    asm volatile("ld.acquire.gpu.u32 %0, [%1];"
                                 : "=r"(cur) : "l"(&g_bar));
                    if (cur < target) __nanosleep(256);
                } while (cur < target);
            }
            __syncthreads();
            // prime layer-2 A pipeline (B2 already in flight as earlier group)
            ISSUE_A(H2, slot, 0, 0);
            CP_COMMIT();
            ISSUE_A(H2, slot, 1, 1);
            CP_COMMIT();
        }
    }
    CP_WAIT(0);
}

// ---------------------------------------------------------------------------
extern "C" void kernel_launch(void* const* d_in, const int* in_sizes, int n_in,
                              void* d_out, int out_size) {
    const float* x  = (const float*)d_in[0];
    const float* t  = (const float*)d_in[1];
    const float* tw = (const float*)d_in[2];
    const float* tb = (const float*)d_in[3];
    const float* W0 = (const float*)d_in[4];
    const float* b0 = (const float*)d_in[5];
    const float* W1 = (const float*)d_in[6];
    const float* b1 = (const float*)d_in[7];
    const float* W2 = (const float*)d_in[8];
    const float* b2 = (const float*)d_in[9];
    float* out = (float*)d_out;

    cudaFuncSetAttribute(k_mma2, cudaFuncAttributeMaxDynamicSharedMemorySize, 229376);

    __half *h1, *h2, *w;
    cudaGetSymbolAddress((void**)&h1, g_h1);
    cudaGetSymbolAddress((void**)&h2, g_h2);
    cudaGetSymbolAddress((void**)&w,  g_W);

    k_prep<<<1408, 256>>>(W1, W2, W0, t, tw, tb, b0);
    k_layer0<<<BSZ * 4, 256>>>(x, W0);
    k_mma2<<<148, 512, 229376>>>(h1, w, b1, b2, h2, out);
}